// round 11
// baseline (speedup 1.0000x reference)
#include <cuda_runtime.h>
#include <cuda_bf16.h>
#include <cstdint>

#define N_NODES 16384
#define KNN 10
#define CAND 16   // approx candidates kept per query for exact rescoring

// ---------------- scratch (static device allocations; no runtime alloc) ----------------
__device__ float d_E [N_NODES * 192];
__device__ float d_H [N_NODES * 128];
__device__ float d_g1[N_NODES * 64];
__device__ float d_g2[N_NODES * 64];
__device__ float d_P [N_NODES * 64];
__device__ float d_Qm[N_NODES * 64];
__device__ float d_sqn[N_NODES];
__device__ int   d_idx[N_NODES * KNN];
__device__ int   d_cand[N_NODES * CAND];
__device__ float d_WP[128 * 64];
__device__ float d_WQ[128 * 64];
__device__ __nv_bfloat16 d_X2[N_NODES * 128];   // bf16(x), up to 128 cols

// ---------------- PTX helpers (generic sm_80+ features only) ----------------
__device__ __forceinline__ uint32_t smem_u32(const void* p) {
    uint32_t a;
    asm("{ .reg .u64 t; cvta.to.shared.u64 t, %1; cvt.u32.u64 %0, t; }" : "=r"(a) : "l"(p));
    return a;
}
#define CP_ASYNC16(dst, src) \
    asm volatile("cp.async.cg.shared.global [%0], [%1], 16;" :: "r"(dst), "l"(src))
#define CP_COMMIT() asm volatile("cp.async.commit_group;" ::: "memory")
#define CP_WAIT0()  asm volatile("cp.async.wait_group 0;" ::: "memory")

#define LDSM4(r0, r1, r2, r3, addr) \
    asm volatile("ldmatrix.sync.aligned.m8n8.x4.shared.b16 {%0,%1,%2,%3}, [%4];" \
                 : "=r"(r0), "=r"(r1), "=r"(r2), "=r"(r3) : "r"(addr))

#define MMA16816(d, a, b) \
    asm volatile("mma.sync.aligned.m16n8k16.row.col.f32.bf16.bf16.f32 " \
                 "{%0,%1,%2,%3}, {%4,%5,%6,%7}, {%8,%9}, {%0,%1,%2,%3};" \
                 : "+f"((d)[0]), "+f"((d)[1]), "+f"((d)[2]), "+f"((d)[3]) \
                 : "r"((a)[0]), "r"((a)[1]), "r"((a)[2]), "r"((a)[3]), \
                   "r"((b)[0]), "r"((b)[1]))

// ---------------- stage 1: per-modality embeds (relu) -> E[N,192] ----------------
__global__ void embed_kernel(const float* __restrict__ nf, const float* __restrict__ rf,
                             const float* __restrict__ tf,
                             const float* __restrict__ Wb, const float* __restrict__ bb,
                             const float* __restrict__ Wr, const float* __restrict__ br,
                             const float* __restrict__ Wt, const float* __restrict__ bt)
{
    __shared__ float s[136];
    const int n = blockIdx.x;
    const int t = threadIdx.x;
    if (t < 8)                 s[t]            = nf[n * 8 + t];
    if (t >= 64 && t < 128)    s[8 + (t - 64)] = rf[n * 64 + (t - 64)];
    if (t >= 128)              s[72 + (t-128)] = tf[n * 64 + (t - 128)];
    __syncthreads();

    float acc;
    if (t < 64) {
        acc = bb[t];
        #pragma unroll
        for (int e = 0; e < 8; e++) acc = fmaf(s[e], Wb[e * 64 + t], acc);
    } else if (t < 128) {
        const int o = t - 64;
        acc = br[o];
        #pragma unroll 8
        for (int e = 0; e < 64; e++) acc = fmaf(s[8 + e], Wr[e * 64 + o], acc);
    } else {
        const int o = t - 128;
        acc = bt[o];
        #pragma unroll 8
        for (int e = 0; e < 64; e++) acc = fmaf(s[72 + e], Wt[e * 64 + o], acc);
    }
    d_E[n * 192 + t] = fmaxf(acc, 0.0f);
}

// ---------------- generic tiled fp32 GEMM ----------------
template <int ACT>
__global__ __launch_bounds__(256) void gemm_kernel(const float* __restrict__ A,
                                                   const float* __restrict__ W,
                                                   const float* __restrict__ bias,
                                                   float* __restrict__ C,
                                                   int Kd, int Nc)
{
    __shared__ float As[16][64];
    __shared__ float Ws[16][64];
    const int m0 = blockIdx.x * 64;
    const int n0 = blockIdx.y * 64;
    const int tid = threadIdx.x;
    const int tx = tid & 15;
    const int ty = tid >> 4;

    float acc[4][4];
    #pragma unroll
    for (int i = 0; i < 4; i++)
        #pragma unroll
        for (int j = 0; j < 4; j++) acc[i][j] = 0.0f;

    for (int k0 = 0; k0 < Kd; k0 += 16) {
        {
            const int m  = tid >> 2;
            const int kq = (tid & 3) * 4;
            float4 v = *reinterpret_cast<const float4*>(&A[(m0 + m) * Kd + k0 + kq]);
            As[kq + 0][m] = v.x; As[kq + 1][m] = v.y;
            As[kq + 2][m] = v.z; As[kq + 3][m] = v.w;
            const int kk = tid >> 4;
            const int nq = (tid & 15) * 4;
            float4 w = *reinterpret_cast<const float4*>(&W[(k0 + kk) * Nc + n0 + nq]);
            *reinterpret_cast<float4*>(&Ws[kk][nq]) = w;
        }
        __syncthreads();
        #pragma unroll
        for (int k = 0; k < 16; k++) {
            float4 a = *reinterpret_cast<const float4*>(&As[k][ty * 4]);
            float4 b = *reinterpret_cast<const float4*>(&Ws[k][tx * 4]);
            float av[4] = {a.x, a.y, a.z, a.w};
            float bv[4] = {b.x, b.y, b.z, b.w};
            #pragma unroll
            for (int i = 0; i < 4; i++)
                #pragma unroll
                for (int j = 0; j < 4; j++)
                    acc[i][j] = fmaf(av[i], bv[j], acc[i][j]);
        }
        __syncthreads();
    }

    #pragma unroll
    for (int i = 0; i < 4; i++) {
        const int m = m0 + ty * 4 + i;
        #pragma unroll
        for (int j = 0; j < 4; j++) {
            const int n = n0 + tx * 4 + j;
            float v = acc[i][j] + (bias ? bias[n] : 0.0f);
            if (ACT == 2) v = (v > 0.0f) ? v : 0.01f * v;
            C[m * Nc + n] = v;
        }
    }
}

// ---------------- fused: bf16 cast (to d_X2) + exact fp32 squared norms ----------
template <int D>
__global__ void splitsq_kernel(const float* __restrict__ X, float* __restrict__ sqn)
{
    constexpr int PL = D / 32;
    const int wid  = threadIdx.x >> 5;
    const int lane = threadIdx.x & 31;
    const int n    = blockIdx.x * 8 + wid;

    float v[PL];
    if constexpr (PL == 4) {
        float4 t = *reinterpret_cast<const float4*>(&X[n * D + lane * 4]);
        v[0] = t.x; v[1] = t.y; v[2] = t.z; v[3] = t.w;
    } else {
        float2 t = *reinterpret_cast<const float2*>(&X[n * D + lane * 2]);
        v[0] = t.x; v[1] = t.y;
    }

    float s = 0.0f;
    #pragma unroll
    for (int i = 0; i < PL; i++) s = fmaf(v[i], v[i], s);
    #pragma unroll
    for (int o = 16; o > 0; o >>= 1) s += __shfl_xor_sync(0xFFFFFFFFu, s, o);
    if (lane == 0) sqn[n] = s;

    if constexpr (PL == 4) {
        __nv_bfloat162 h0 = __floats2bfloat162_rn(v[0], v[1]);
        __nv_bfloat162 h1 = __floats2bfloat162_rn(v[2], v[3]);
        *reinterpret_cast<__nv_bfloat162*>(&d_X2[n * D + lane * 4])     = h0;
        *reinterpret_cast<__nv_bfloat162*>(&d_X2[n * D + lane * 4 + 2]) = h1;
    } else {
        __nv_bfloat162 h0 = __floats2bfloat162_rn(v[0], v[1]);
        *reinterpret_cast<__nv_bfloat162*>(&d_X2[n * D + lane * 2]) = h0;
    }
}

// ---------------- top-k insert (generic length) ----------------
template <int M>
__device__ __forceinline__ void topk_insert(float (&topd)[M], int (&topi)[M],
                                            float dd, int ci)
{
    topd[M - 1] = dd; topi[M - 1] = ci;
    #pragma unroll
    for (int z = M - 2; z >= 0; z--) {
        if (topd[z] > topd[z + 1]) {
            float td = topd[z]; topd[z] = topd[z + 1]; topd[z + 1] = td;
            int   ti = topi[z]; topi[z] = topi[z + 1]; topi[z + 1] = ti;
        }
    }
}

// ---------------- approx KNN via mma.sync (single-term bf16 Gram), 512 threads ----
// 128 queries/block, 128-candidate tiles, 16 warps; warp = 32q x 32c patch.
// fp32 dist, single buffer; argmin-loop scan guarded by a per-(row,group)
// min prefilter computed (via shuffles) during the dist-write phase.
template <int D>
__global__ __launch_bounds__(512, 1) void knn_mma_kernel(const float* __restrict__ sqn,
                                                         int* __restrict__ outCand)
{
    constexpr int PAD   = 8;
    constexpr int PB    = (D + PAD) * 2;        // tile smem row pitch in bytes
    constexpr int TILEB = 128 * PB;
    constexpr int CH    = D / 8;                // 16B chunks per row

    extern __shared__ char smch[];
    char* qt  = smch;
    char* ct0 = smch + TILEB;
    char* ct1 = smch + 2 * TILEB;
    float* dist = reinterpret_cast<float*>(smch + 3 * TILEB);  // 128*132 floats

    __shared__ float s_sqc[2][128];
    __shared__ float s_rmin[128][4];            // per-(query,32-col group) tile min
    __shared__ float s_mg [128 * CAND];
    __shared__ int   s_mgi[128 * CAND];

    const int tid  = threadIdx.x;
    const int wid  = tid >> 5;
    const int lane = tid & 31;
    const int q0   = blockIdx.x * 128;

    const int mrow = (wid & 3) * 32;            // warp's query-row base
    const int ncol = (wid >> 2) * 32;           // warp's candidate-col base
    const int wgrp = wid >> 2;                  // warp's col-group id (0..3)
    const int lrow = lane & 15;
    const int lkof = (lane >> 4) * 16;

    const uint32_t qtu  = smem_u32(qt);
    const uint32_t ctu0 = smem_u32(ct0);
    const uint32_t ctu1 = smem_u32(ct1);
    const uint32_t aBase = qtu + (mrow + lrow) * PB + lkof;
    const uint32_t bOff  = (ncol + lrow) * PB + lkof;

    {
        #pragma unroll
        for (int i = tid; i < 128 * CH; i += 512) {
            const int r  = i / CH;
            const int ch = i - r * CH;
            CP_ASYNC16(qtu + r * PB + ch * 16,
                       d_X2 + (size_t)(q0 + r) * D + ch * 8);
        }
        #pragma unroll
        for (int i = tid; i < 128 * CH; i += 512) {
            const int r  = i / CH;
            const int ch = i - r * CH;
            CP_ASYNC16(ctu0 + r * PB + ch * 16,
                       d_X2 + (size_t)r * D + ch * 8);
        }
        CP_COMMIT();
        if (tid < 128) s_sqc[0][tid] = sqn[tid];
    }

    float topd[CAND]; int topi[CAND];
    #pragma unroll
    for (int i = 0; i < CAND; i++) { topd[i] = 1e30f; topi[i] = 0; }

    const int qmine = tid & 127;     // query owned for scanning
    const int grp   = tid >> 7;      // 0..3: quarter of the candidate tile
    const int cbase = grp * 32;

    // argmin-loop scan of this thread's 32-candidate segment (tile base cp0),
    // short-circuited by the row-group min prefilter.
    float* const myrow = &dist[(tid & 127) * 132 + cbase];
    auto scan_row = [&](int cp0) {
        if (s_rmin[qmine][grp] >= topd[CAND - 1]) return;   // nothing can qualify
        while (true) {
            float bm = 1e30f; int ba = 0;
            #pragma unroll
            for (int cc = 0; cc < 8; cc++) {
                float4 v = *reinterpret_cast<const float4*>(&myrow[cc * 4]);
                if (v.x < bm) { bm = v.x; ba = cc * 4 + 0; }
                if (v.y < bm) { bm = v.y; ba = cc * 4 + 1; }
                if (v.z < bm) { bm = v.z; ba = cc * 4 + 2; }
                if (v.w < bm) { bm = v.w; ba = cc * 4 + 3; }
            }
            if (bm >= topd[CAND - 1]) break;
            topk_insert(topd, topi, bm, cp0 + cbase + ba);
            myrow[ba] = 1e30f;   // remove from pool (thread-exclusive segment)
        }
    };

    const int T = N_NODES / 128;
    for (int t = 0; t < T; t++) {
        CP_WAIT0();
        __syncthreads();   // ct(t) resident; dist(t-1)+rmin(t-1) writes visible

        const uint32_t ctu = (t & 1) ? ctu1 : ctu0;
        if (t + 1 < T) {
            const uint32_t ctn = ((t + 1) & 1) ? ctu1 : ctu0;
            const int r0n = (t + 1) * 128;
            #pragma unroll
            for (int i = tid; i < 128 * CH; i += 512) {
                const int r  = i / CH;
                const int ch = i - r * CH;
                CP_ASYNC16(ctn + r * PB + ch * 16,
                           d_X2 + (size_t)(r0n + r) * D + ch * 8);
            }
            CP_COMMIT();
            if (tid < 128) s_sqc[(t + 1) & 1][tid] = sqn[r0n + tid];
        }

        // ---- Gram: warp 32q x 32c, m16n8k16 atoms ----
        float acc[2][4][4];
        #pragma unroll
        for (int mt = 0; mt < 2; mt++)
            #pragma unroll
            for (int nt = 0; nt < 4; nt++)
                #pragma unroll
                for (int r = 0; r < 4; r++) acc[mt][nt][r] = 0.0f;

        const uint32_t bBase = ctu + bOff;
        #pragma unroll
        for (int kc = 0; kc < D; kc += 16) {
            uint32_t a[2][4];
            #pragma unroll
            for (int mt = 0; mt < 2; mt++)
                LDSM4(a[mt][0], a[mt][1], a[mt][2], a[mt][3],
                      aBase + mt * 16 * PB + kc * 2);
            uint32_t b[4][2];
            #pragma unroll
            for (int nb = 0; nb < 2; nb++) {
                uint32_t r0, r1, r2, r3;
                LDSM4(r0, r1, r2, r3, bBase + nb * 16 * PB + kc * 2);
                b[nb * 2][0] = r0; b[nb * 2][1] = r2;
                b[nb * 2 + 1][0] = r1; b[nb * 2 + 1][1] = r3;
            }
            #pragma unroll
            for (int mt = 0; mt < 2; mt++)
                #pragma unroll
                for (int nt = 0; nt < 4; nt++)
                    MMA16816(acc[mt][nt], a[mt], b[nt]);
        }

        // ---- scan dist(t-1) — independent of MMA(t); fills its latency ----
        if (t > 0) scan_row((t - 1) * 128);
        __syncthreads();   // all scans done before dist/rmin rewrite

        // ---- write dist(t) fp32 + row-group min prefilter ----
        const float* sq = s_sqc[t & 1];
        const int c0 = t * 128;

        #pragma unroll
        for (int mt = 0; mt < 2; mt++) {
            const int qA = mrow + mt * 16 + (lane >> 2);
            float m0 = 1e30f, m1 = 1e30f;
            #pragma unroll
            for (int nt = 0; nt < 4; nt++) {
                const int c = ncol + nt * 8 + (lane & 3) * 2;
                const float s0 = sq[c], s1 = sq[c + 1];
                float2 v0, v1;
                v0.x = fmaf(-2.0f, acc[mt][nt][0], s0);
                v0.y = fmaf(-2.0f, acc[mt][nt][1], s1);
                v1.x = fmaf(-2.0f, acc[mt][nt][2], s0);
                v1.y = fmaf(-2.0f, acc[mt][nt][3], s1);
                const int dq = (q0 + qA) - (c0 + c);
                if (dq ==  0) v0.x = 1e30f;
                if (dq ==  1) v0.y = 1e30f;
                if (dq == -8) v1.x = 1e30f;
                if (dq == -7) v1.y = 1e30f;
                m0 = fminf(m0, fminf(v0.x, v0.y));
                m1 = fminf(m1, fminf(v1.x, v1.y));
                *reinterpret_cast<float2*>(&dist[qA * 132 + c])       = v0;
                *reinterpret_cast<float2*>(&dist[(qA + 8) * 132 + c]) = v1;
            }
            // reduce across the 4 lanes covering this row's 32 cols (lane&3 quad)
            m0 = fminf(m0, __shfl_xor_sync(0xFFFFFFFFu, m0, 1));
            m0 = fminf(m0, __shfl_xor_sync(0xFFFFFFFFu, m0, 2));
            m1 = fminf(m1, __shfl_xor_sync(0xFFFFFFFFu, m1, 1));
            m1 = fminf(m1, __shfl_xor_sync(0xFFFFFFFFu, m1, 2));
            if ((lane & 3) == 0) {
                s_rmin[qA][wgrp]     = m0;
                s_rmin[qA + 8][wgrp] = m1;
            }
        }
    }

    // final tile's scan
    __syncthreads();
    scan_row((T - 1) * 128);

    // ---- merge the four per-query quarters (3 rounds through one buffer) ----
    #pragma unroll 1
    for (int s = 1; s < 4; s++) {
        __syncthreads();
        if (grp == s) {
            #pragma unroll
            for (int i = 0; i < CAND; i++) {
                s_mg [qmine * CAND + i] = topd[i];
                s_mgi[qmine * CAND + i] = topi[i];
            }
        }
        __syncthreads();
        if (grp == 0) {
            #pragma unroll
            for (int i = 0; i < CAND; i++) {
                const float dd = s_mg[qmine * CAND + i];
                if (dd < topd[CAND - 1]) topk_insert(topd, topi, dd, s_mgi[qmine * CAND + i]);
            }
        }
    }
    if (grp == 0) {
        #pragma unroll
        for (int i = 0; i < CAND; i++) outCand[(q0 + qmine) * CAND + i] = topi[i];
    }
}

// ---------------- exact fp32 rescore: top-KNN of CAND candidates per query -------
template <int D>
__global__ void rescore_kernel(const float* __restrict__ X, const float* __restrict__ sqn,
                               const int* __restrict__ cand, int* __restrict__ outIdx)
{
    constexpr int PL = D / 32;
    const int wid  = threadIdx.x >> 5;
    const int lane = threadIdx.x & 31;
    const int q    = blockIdx.x * 8 + wid;

    float xq[PL];
    #pragma unroll
    for (int i = 0; i < PL; i++) xq[i] = X[q * D + i * 32 + lane];

    float topd[KNN]; int topi[KNN];
    #pragma unroll
    for (int i = 0; i < KNN; i++) { topd[i] = 1e30f; topi[i] = 0; }

    #pragma unroll
    for (int j = 0; j < CAND; j++) {
        const int c = cand[q * CAND + j];
        float dot = 0.0f;
        #pragma unroll
        for (int i = 0; i < PL; i++) dot = fmaf(xq[i], X[c * D + i * 32 + lane], dot);
        #pragma unroll
        for (int o = 16; o > 0; o >>= 1) dot += __shfl_xor_sync(0xFFFFFFFFu, dot, o);
        const float dd = fmaf(-2.0f, dot, sqn[c]);
        if (dd < topd[KNN - 1]) topk_insert(topd, topi, dd, c);
    }
    if (lane == 0) {
        #pragma unroll
        for (int i = 0; i < KNN; i++) outIdx[q * KNN + i] = topi[i];
    }
}

// ---------------- EdgeConv weight split: WP = Wa - Wb, WQ = Wb ----------------
__global__ void prepw_kernel(const float* __restrict__ We, int D)
{
    const int i = blockIdx.x * 256 + threadIdx.x;
    if (i < D * 64) {
        const float b = We[D * 64 + i];
        d_WQ[i] = b;
        d_WP[i] = We[i] - b;
    }
}

// ---------------- EdgeConv aggregation ----------------
__global__ void maxagg_kernel(const float* __restrict__ P, const float* __restrict__ Q,
                              const int* __restrict__ idx, float* __restrict__ g)
{
    const int tid = threadIdx.x;
    const int n = blockIdx.x * 4 + (tid >> 6);
    const int o = tid & 63;
    const float p = P[n * 64 + o];
    float m = -1e30f;
    #pragma unroll
    for (int kk = 0; kk < KNN; kk++) {
        const int j = idx[n * KNN + kk];
        float v = p + Q[j * 64 + o];
        v = (v > 0.0f) ? v : 0.01f * v;
        m = fmaxf(m, v);
    }
    g[n * 64 + o] = m;
}

// ---------------- classifier ----------------
__global__ void classifier_kernel(const float* __restrict__ Wc, const float* __restrict__ bc,
                                  float* __restrict__ out)
{
    const int tid = threadIdx.x;
    const int n = blockIdx.x * 16 + (tid >> 4);
    const int c = tid & 15;
    float acc = bc[c];
    const float* g1r = d_g1 + n * 64;
    const float* g2r = d_g2 + n * 64;
    #pragma unroll 8
    for (int o = 0; o < 64; o++) {
        acc = fmaf(g1r[o], Wc[o * 16 + c], acc);
        acc = fmaf(g2r[o], Wc[(64 + o) * 16 + c], acc);
    }
    out[n * 16 + c] = acc;
}

// ---------------- launch ----------------
extern "C" void kernel_launch(void* const* d_in, const int* in_sizes, int n_in,
                              void* d_out, int out_size)
{
    const float* node_feat = (const float*)d_in[0];
    const float* rf_feat   = (const float*)d_in[1];
    const float* txp_feat  = (const float*)d_in[2];
    const float* Wb  = (const float*)d_in[3];
    const float* bb  = (const float*)d_in[4];
    const float* Wr  = (const float*)d_in[5];
    const float* br  = (const float*)d_in[6];
    const float* Wt  = (const float*)d_in[7];
    const float* bt  = (const float*)d_in[8];
    const float* Wf  = (const float*)d_in[9];
    const float* bf  = (const float*)d_in[10];
    const float* We1 = (const float*)d_in[11];
    const float* be1 = (const float*)d_in[12];
    const float* We2 = (const float*)d_in[13];
    const float* be2 = (const float*)d_in[14];
    const float* Wc  = (const float*)d_in[15];
    const float* bc  = (const float*)d_in[16];
    float* out = (float*)d_out;

    void *pE, *pH, *pg1, *pg2, *pP, *pQ, *psqn, *pidx, *pcand, *pWP, *pWQ;
    cudaGetSymbolAddress(&pE,    d_E);
    cudaGetSymbolAddress(&pH,    d_H);
    cudaGetSymbolAddress(&pg1,   d_g1);
    cudaGetSymbolAddress(&pg2,   d_g2);
    cudaGetSymbolAddress(&pP,    d_P);
    cudaGetSymbolAddress(&pQ,    d_Qm);
    cudaGetSymbolAddress(&psqn,  d_sqn);
    cudaGetSymbolAddress(&pidx,  d_idx);
    cudaGetSymbolAddress(&pcand, d_cand);
    cudaGetSymbolAddress(&pWP,   d_WP);
    cudaGetSymbolAddress(&pWQ,   d_WQ);

    // D=128: 3 tiles x 34816B + fp32 dist 67584B = 172032B dynamic
    // D=64 : 3 tiles x 18432B + fp32 dist 67584B = 122880B dynamic
    const int smem1 = 3 * 128 * 272 + 128 * 132 * 4;
    const int smem2 = 3 * 128 * 144 + 128 * 132 * 4;
    cudaFuncSetAttribute(knn_mma_kernel<128>, cudaFuncAttributeMaxDynamicSharedMemorySize, smem1);
    cudaFuncSetAttribute(knn_mma_kernel<64>,  cudaFuncAttributeMaxDynamicSharedMemorySize, smem2);

    // stage 1: embeds + fusion   (launch order keeps knn<128> at profiled slot #4)
    embed_kernel<<<N_NODES, 192>>>(node_feat, rf_feat, txp_feat, Wb, bb, Wr, br, Wt, bt);
    gemm_kernel<2><<<dim3(N_NODES / 64, 2), 256>>>((const float*)pE, Wf, bf, (float*)pH, 192, 128);

    // EdgeConv 1
    splitsq_kernel<128><<<N_NODES / 8, 256>>>((const float*)pH, (float*)psqn);
    knn_mma_kernel<128><<<128, 512, smem1>>>((const float*)psqn, (int*)pcand);
    rescore_kernel<128><<<N_NODES / 8, 256>>>((const float*)pH, (const float*)psqn,
                                              (const int*)pcand, (int*)pidx);
    prepw_kernel<<<(128 * 64 + 255) / 256, 256>>>(We1, 128);
    gemm_kernel<0><<<dim3(N_NODES / 64, 1), 256>>>((const float*)pH, (const float*)pWP, be1,
                                                   (float*)pP, 128, 64);
    gemm_kernel<0><<<dim3(N_NODES / 64, 1), 256>>>((const float*)pH, (const float*)pWQ, nullptr,
                                                   (float*)pQ, 128, 64);
    maxagg_kernel<<<N_NODES / 4, 256>>>((const float*)pP, (const float*)pQ,
                                        (const int*)pidx, (float*)pg1);

    // EdgeConv 2
    splitsq_kernel<64><<<N_NODES / 8, 256>>>((const float*)pg1, (float*)psqn);
    knn_mma_kernel<64><<<128, 512, smem2>>>((const float*)psqn, (int*)pcand);
    rescore_kernel<64><<<N_NODES / 8, 256>>>((const float*)pg1, (const float*)psqn,
                                             (const int*)pcand, (int*)pidx);
    prepw_kernel<<<(64 * 64 + 255) / 256, 256>>>(We2, 64);
    gemm_kernel<0><<<dim3(N_NODES / 64, 1), 256>>>((const float*)pg1, (const float*)pWP, be2,
                                                   (float*)pP, 64, 64);
    gemm_kernel<0><<<dim3(N_NODES / 64, 1), 256>>>((const float*)pg1, (const float*)pWQ, nullptr,
                                                   (float*)pQ, 64, 64);
    maxagg_kernel<<<N_NODES / 4, 256>>>((const float*)pP, (const float*)pQ,
                                        (const int*)pidx, (float*)pg2);

    // classifier
    classifier_kernel<<<N_NODES / 16, 256>>>(Wc, bc, out);
}

// round 12
// speedup vs baseline: 1.0376x; 1.0376x over previous
#include <cuda_runtime.h>
#include <cuda_bf16.h>
#include <cstdint>

#define N_NODES 16384
#define KNN 10
#define CAND 16   // approx candidates kept per query for exact rescoring

// ---------------- scratch (static device allocations; no runtime alloc) ----------------
__device__ float d_E [N_NODES * 192];
__device__ float d_H [N_NODES * 128];
__device__ float d_g1[N_NODES * 64];
__device__ float d_g2[N_NODES * 64];
__device__ float d_P [N_NODES * 64];
__device__ float d_Qm[N_NODES * 64];
__device__ float d_sqn[N_NODES];
__device__ int   d_idx[N_NODES * KNN];
__device__ int   d_cand[N_NODES * CAND];
__device__ float d_WP[128 * 64];
__device__ float d_WQ[128 * 64];
__device__ __nv_bfloat16 d_X2[N_NODES * 128];   // bf16(x), up to 128 cols

// ---------------- PTX helpers (generic sm_80+ features only) ----------------
__device__ __forceinline__ uint32_t smem_u32(const void* p) {
    uint32_t a;
    asm("{ .reg .u64 t; cvta.to.shared.u64 t, %1; cvt.u32.u64 %0, t; }" : "=r"(a) : "l"(p));
    return a;
}
#define CP_ASYNC16(dst, src) \
    asm volatile("cp.async.cg.shared.global [%0], [%1], 16;" :: "r"(dst), "l"(src))
#define CP_COMMIT() asm volatile("cp.async.commit_group;" ::: "memory")
#define CP_WAIT0()  asm volatile("cp.async.wait_group 0;" ::: "memory")

#define LDSM4(r0, r1, r2, r3, addr) \
    asm volatile("ldmatrix.sync.aligned.m8n8.x4.shared.b16 {%0,%1,%2,%3}, [%4];" \
                 : "=r"(r0), "=r"(r1), "=r"(r2), "=r"(r3) : "r"(addr))

#define MMA16816(d, a, b) \
    asm volatile("mma.sync.aligned.m16n8k16.row.col.f32.bf16.bf16.f32 " \
                 "{%0,%1,%2,%3}, {%4,%5,%6,%7}, {%8,%9}, {%0,%1,%2,%3};" \
                 : "+f"((d)[0]), "+f"((d)[1]), "+f"((d)[2]), "+f"((d)[3]) \
                 : "r"((a)[0]), "r"((a)[1]), "r"((a)[2]), "r"((a)[3]), \
                   "r"((b)[0]), "r"((b)[1]))

// ---------------- stage 1: per-modality embeds (relu) -> E[N,192] ----------------
__global__ void embed_kernel(const float* __restrict__ nf, const float* __restrict__ rf,
                             const float* __restrict__ tf,
                             const float* __restrict__ Wb, const float* __restrict__ bb,
                             const float* __restrict__ Wr, const float* __restrict__ br,
                             const float* __restrict__ Wt, const float* __restrict__ bt)
{
    __shared__ float s[136];
    const int n = blockIdx.x;
    const int t = threadIdx.x;
    if (t < 8)                 s[t]            = nf[n * 8 + t];
    if (t >= 64 && t < 128)    s[8 + (t - 64)] = rf[n * 64 + (t - 64)];
    if (t >= 128)              s[72 + (t-128)] = tf[n * 64 + (t - 128)];
    __syncthreads();

    float acc;
    if (t < 64) {
        acc = bb[t];
        #pragma unroll
        for (int e = 0; e < 8; e++) acc = fmaf(s[e], Wb[e * 64 + t], acc);
    } else if (t < 128) {
        const int o = t - 64;
        acc = br[o];
        #pragma unroll 8
        for (int e = 0; e < 64; e++) acc = fmaf(s[8 + e], Wr[e * 64 + o], acc);
    } else {
        const int o = t - 128;
        acc = bt[o];
        #pragma unroll 8
        for (int e = 0; e < 64; e++) acc = fmaf(s[72 + e], Wt[e * 64 + o], acc);
    }
    d_E[n * 192 + t] = fmaxf(acc, 0.0f);
}

// ---------------- generic tiled fp32 GEMM ----------------
template <int ACT>
__global__ __launch_bounds__(256) void gemm_kernel(const float* __restrict__ A,
                                                   const float* __restrict__ W,
                                                   const float* __restrict__ bias,
                                                   float* __restrict__ C,
                                                   int Kd, int Nc)
{
    __shared__ float As[16][64];
    __shared__ float Ws[16][64];
    const int m0 = blockIdx.x * 64;
    const int n0 = blockIdx.y * 64;
    const int tid = threadIdx.x;
    const int tx = tid & 15;
    const int ty = tid >> 4;

    float acc[4][4];
    #pragma unroll
    for (int i = 0; i < 4; i++)
        #pragma unroll
        for (int j = 0; j < 4; j++) acc[i][j] = 0.0f;

    for (int k0 = 0; k0 < Kd; k0 += 16) {
        {
            const int m  = tid >> 2;
            const int kq = (tid & 3) * 4;
            float4 v = *reinterpret_cast<const float4*>(&A[(m0 + m) * Kd + k0 + kq]);
            As[kq + 0][m] = v.x; As[kq + 1][m] = v.y;
            As[kq + 2][m] = v.z; As[kq + 3][m] = v.w;
            const int kk = tid >> 4;
            const int nq = (tid & 15) * 4;
            float4 w = *reinterpret_cast<const float4*>(&W[(k0 + kk) * Nc + n0 + nq]);
            *reinterpret_cast<float4*>(&Ws[kk][nq]) = w;
        }
        __syncthreads();
        #pragma unroll
        for (int k = 0; k < 16; k++) {
            float4 a = *reinterpret_cast<const float4*>(&As[k][ty * 4]);
            float4 b = *reinterpret_cast<const float4*>(&Ws[k][tx * 4]);
            float av[4] = {a.x, a.y, a.z, a.w};
            float bv[4] = {b.x, b.y, b.z, b.w};
            #pragma unroll
            for (int i = 0; i < 4; i++)
                #pragma unroll
                for (int j = 0; j < 4; j++)
                    acc[i][j] = fmaf(av[i], bv[j], acc[i][j]);
        }
        __syncthreads();
    }

    #pragma unroll
    for (int i = 0; i < 4; i++) {
        const int m = m0 + ty * 4 + i;
        #pragma unroll
        for (int j = 0; j < 4; j++) {
            const int n = n0 + tx * 4 + j;
            float v = acc[i][j] + (bias ? bias[n] : 0.0f);
            if (ACT == 2) v = (v > 0.0f) ? v : 0.01f * v;
            C[m * Nc + n] = v;
        }
    }
}

// ---------------- fused: bf16 cast (to d_X2) + exact fp32 squared norms ----------
template <int D>
__global__ void splitsq_kernel(const float* __restrict__ X, float* __restrict__ sqn)
{
    constexpr int PL = D / 32;
    const int wid  = threadIdx.x >> 5;
    const int lane = threadIdx.x & 31;
    const int n    = blockIdx.x * 8 + wid;

    float v[PL];
    if constexpr (PL == 4) {
        float4 t = *reinterpret_cast<const float4*>(&X[n * D + lane * 4]);
        v[0] = t.x; v[1] = t.y; v[2] = t.z; v[3] = t.w;
    } else {
        float2 t = *reinterpret_cast<const float2*>(&X[n * D + lane * 2]);
        v[0] = t.x; v[1] = t.y;
    }

    float s = 0.0f;
    #pragma unroll
    for (int i = 0; i < PL; i++) s = fmaf(v[i], v[i], s);
    #pragma unroll
    for (int o = 16; o > 0; o >>= 1) s += __shfl_xor_sync(0xFFFFFFFFu, s, o);
    if (lane == 0) sqn[n] = s;

    if constexpr (PL == 4) {
        __nv_bfloat162 h0 = __floats2bfloat162_rn(v[0], v[1]);
        __nv_bfloat162 h1 = __floats2bfloat162_rn(v[2], v[3]);
        *reinterpret_cast<__nv_bfloat162*>(&d_X2[n * D + lane * 4])     = h0;
        *reinterpret_cast<__nv_bfloat162*>(&d_X2[n * D + lane * 4 + 2]) = h1;
    } else {
        __nv_bfloat162 h0 = __floats2bfloat162_rn(v[0], v[1]);
        *reinterpret_cast<__nv_bfloat162*>(&d_X2[n * D + lane * 2]) = h0;
    }
}

// ---------------- top-k insert (generic length) ----------------
template <int M>
__device__ __forceinline__ void topk_insert(float (&topd)[M], int (&topi)[M],
                                            float dd, int ci)
{
    topd[M - 1] = dd; topi[M - 1] = ci;
    #pragma unroll
    for (int z = M - 2; z >= 0; z--) {
        if (topd[z] > topd[z + 1]) {
            float td = topd[z]; topd[z] = topd[z + 1]; topd[z + 1] = td;
            int   ti = topi[z]; topi[z] = topi[z + 1]; topi[z + 1] = ti;
        }
    }
}

// ---------------- approx KNN via mma.sync (single-term bf16 Gram), 512 threads ----
// 128 queries/block, 128-candidate tiles, 16 warps; warp = 32q x 32c patch.
// fp32 dist, single buffer; fmin-tree fast-path + argmin insert loop;
// diagonal self-exclusion gated to the single tile where q0 == c0.
template <int D>
__global__ __launch_bounds__(512, 1) void knn_mma_kernel(const float* __restrict__ sqn,
                                                         int* __restrict__ outCand)
{
    constexpr int PAD   = 8;
    constexpr int PB    = (D + PAD) * 2;        // tile smem row pitch in bytes
    constexpr int TILEB = 128 * PB;
    constexpr int CH    = D / 8;                // 16B chunks per row
    constexpr int RPI   = 512 / CH;             // rows covered per load iteration
    constexpr int NIT   = 128 / RPI;            // load iterations per tile

    extern __shared__ char smch[];
    char* qt  = smch;
    char* ct0 = smch + TILEB;
    char* ct1 = smch + 2 * TILEB;
    float* dist = reinterpret_cast<float*>(smch + 3 * TILEB);  // 128*132 floats

    __shared__ float s_sqc[2][128];
    __shared__ float s_mg [128 * CAND];
    __shared__ int   s_mgi[128 * CAND];

    const int tid  = threadIdx.x;
    const int wid  = tid >> 5;
    const int lane = tid & 31;
    const int q0   = blockIdx.x * 128;

    const int mrow = (wid & 3) * 32;            // warp's query-row base
    const int ncol = (wid >> 2) * 32;           // warp's candidate-col base
    const int lrow = lane & 15;
    const int lkof = (lane >> 4) * 16;

    // loop-invariant load addressing: this thread always loads row r0c + j*RPI, chunk ch0
    const int r0c = tid / CH;
    const int ch0 = tid % CH;

    const uint32_t qtu  = smem_u32(qt);
    const uint32_t ctu0 = smem_u32(ct0);
    const uint32_t ctu1 = smem_u32(ct1);
    const uint32_t aBase = qtu + (mrow + lrow) * PB + lkof;
    const uint32_t bOff  = (ncol + lrow) * PB + lkof;
    const uint32_t ldOff = r0c * PB + ch0 * 16;          // smem offset of this thread's chunk

    {
        const __nv_bfloat16* srcQ = d_X2 + (size_t)(q0 + r0c) * D + ch0 * 8;
        const __nv_bfloat16* srcC = d_X2 + (size_t)r0c * D + ch0 * 8;
        #pragma unroll
        for (int j = 0; j < NIT; j++)
            CP_ASYNC16(qtu + ldOff + j * (RPI * PB), srcQ + (size_t)j * RPI * D);
        #pragma unroll
        for (int j = 0; j < NIT; j++)
            CP_ASYNC16(ctu0 + ldOff + j * (RPI * PB), srcC + (size_t)j * RPI * D);
        CP_COMMIT();
        if (tid < 128) s_sqc[0][tid] = sqn[tid];
    }

    float topd[CAND]; int topi[CAND];
    #pragma unroll
    for (int i = 0; i < CAND; i++) { topd[i] = 1e30f; topi[i] = 0; }

    const int qmine = tid & 127;     // query owned for scanning
    const int grp   = tid >> 7;      // 0..3: quarter of the candidate tile
    const int cbase = grp * 32;

    // scan this thread's 32-candidate segment (tile base cp0):
    // fmin-tree fast path; argmin-loop with single insert site when needed.
    float* const myrow = &dist[(tid & 127) * 132 + cbase];
    auto scan_row = [&](int cp0) {
        float m0 = 1e30f, m1 = 1e30f;
        #pragma unroll
        for (int cc = 0; cc < 8; cc += 2) {
            float4 v0 = *reinterpret_cast<const float4*>(&myrow[cc * 4]);
            float4 v1 = *reinterpret_cast<const float4*>(&myrow[cc * 4 + 4]);
            m0 = fminf(m0, fminf(fminf(v0.x, v0.y), fminf(v0.z, v0.w)));
            m1 = fminf(m1, fminf(fminf(v1.x, v1.y), fminf(v1.z, v1.w)));
        }
        if (fminf(m0, m1) >= topd[CAND - 1]) return;    // nothing qualifies
        while (true) {
            float bm = 1e30f; int ba = 0;
            #pragma unroll
            for (int cc = 0; cc < 8; cc++) {
                float4 v = *reinterpret_cast<const float4*>(&myrow[cc * 4]);
                if (v.x < bm) { bm = v.x; ba = cc * 4 + 0; }
                if (v.y < bm) { bm = v.y; ba = cc * 4 + 1; }
                if (v.z < bm) { bm = v.z; ba = cc * 4 + 2; }
                if (v.w < bm) { bm = v.w; ba = cc * 4 + 3; }
            }
            if (bm >= topd[CAND - 1]) break;
            topk_insert(topd, topi, bm, cp0 + cbase + ba);
            myrow[ba] = 1e30f;   // remove from pool (thread-exclusive segment)
        }
    };

    const int T = N_NODES / 128;
    for (int t = 0; t < T; t++) {
        CP_WAIT0();
        __syncthreads();   // ct(t) resident; dist(t-1) writes visible

        const uint32_t ctu = (t & 1) ? ctu1 : ctu0;
        if (t + 1 < T) {
            const uint32_t ctn = ((t + 1) & 1) ? ctu1 : ctu0;
            const __nv_bfloat16* srcC =
                d_X2 + (size_t)((t + 1) * 128 + r0c) * D + ch0 * 8;
            #pragma unroll
            for (int j = 0; j < NIT; j++)
                CP_ASYNC16(ctn + ldOff + j * (RPI * PB), srcC + (size_t)j * RPI * D);
            CP_COMMIT();
            if (tid < 128) s_sqc[(t + 1) & 1][tid] = sqn[(t + 1) * 128 + tid];
        }

        // ---- Gram: warp 32q x 32c, m16n8k16 atoms ----
        float acc[2][4][4];
        #pragma unroll
        for (int mt = 0; mt < 2; mt++)
            #pragma unroll
            for (int nt = 0; nt < 4; nt++)
                #pragma unroll
                for (int r = 0; r < 4; r++) acc[mt][nt][r] = 0.0f;

        const uint32_t bBase = ctu + bOff;
        #pragma unroll
        for (int kc = 0; kc < D; kc += 16) {
            uint32_t a[2][4];
            #pragma unroll
            for (int mt = 0; mt < 2; mt++)
                LDSM4(a[mt][0], a[mt][1], a[mt][2], a[mt][3],
                      aBase + mt * 16 * PB + kc * 2);
            uint32_t b[4][2];
            #pragma unroll
            for (int nb = 0; nb < 2; nb++) {
                uint32_t r0, r1, r2, r3;
                LDSM4(r0, r1, r2, r3, bBase + nb * 16 * PB + kc * 2);
                b[nb * 2][0] = r0; b[nb * 2][1] = r2;
                b[nb * 2 + 1][0] = r1; b[nb * 2 + 1][1] = r3;
            }
            #pragma unroll
            for (int mt = 0; mt < 2; mt++)
                #pragma unroll
                for (int nt = 0; nt < 4; nt++)
                    MMA16816(acc[mt][nt], a[mt], b[nt]);
        }

        // ---- scan dist(t-1) — independent of MMA(t); fills its latency ----
        if (t > 0) scan_row((t - 1) * 128);
        __syncthreads();   // all scans done before dist rewrite

        // ---- write dist(t), fp32; diagonal handling only in the matching tile ----
        const float* sq = s_sqc[t & 1];
        const int c0 = t * 128;
        const bool diag = (c0 == q0);

        #pragma unroll
        for (int mt = 0; mt < 2; mt++) {
            const int qA = mrow + mt * 16 + (lane >> 2);
            #pragma unroll
            for (int nt = 0; nt < 4; nt++) {
                const int c = ncol + nt * 8 + (lane & 3) * 2;
                const float s0 = sq[c], s1 = sq[c + 1];
                float2 v0, v1;
                v0.x = fmaf(-2.0f, acc[mt][nt][0], s0);
                v0.y = fmaf(-2.0f, acc[mt][nt][1], s1);
                v1.x = fmaf(-2.0f, acc[mt][nt][2], s0);
                v1.y = fmaf(-2.0f, acc[mt][nt][3], s1);
                if (diag) {   // self-exclusion possible only when q0 == c0
                    const int dq = qA - c;
                    if (dq ==  0) v0.x = 1e30f;
                    if (dq ==  1) v0.y = 1e30f;
                    if (dq == -8) v1.x = 1e30f;
                    if (dq == -7) v1.y = 1e30f;
                }
                *reinterpret_cast<float2*>(&dist[qA * 132 + c])       = v0;
                *reinterpret_cast<float2*>(&dist[(qA + 8) * 132 + c]) = v1;
            }
        }
    }

    // final tile's scan
    __syncthreads();
    scan_row((T - 1) * 128);

    // ---- merge the four per-query quarters (3 rounds through one buffer) ----
    #pragma unroll 1
    for (int s = 1; s < 4; s++) {
        __syncthreads();
        if (grp == s) {
            #pragma unroll
            for (int i = 0; i < CAND; i++) {
                s_mg [qmine * CAND + i] = topd[i];
                s_mgi[qmine * CAND + i] = topi[i];
            }
        }
        __syncthreads();
        if (grp == 0) {
            #pragma unroll
            for (int i = 0; i < CAND; i++) {
                const float dd = s_mg[qmine * CAND + i];
                if (dd < topd[CAND - 1]) topk_insert(topd, topi, dd, s_mgi[qmine * CAND + i]);
            }
        }
    }
    if (grp == 0) {
        #pragma unroll
        for (int i = 0; i < CAND; i++) outCand[(q0 + qmine) * CAND + i] = topi[i];
    }
}

// ---------------- exact fp32 rescore: top-KNN of CAND candidates per query -------
template <int D>
__global__ void rescore_kernel(const float* __restrict__ X, const float* __restrict__ sqn,
                               const int* __restrict__ cand, int* __restrict__ outIdx)
{
    constexpr int PL = D / 32;
    const int wid  = threadIdx.x >> 5;
    const int lane = threadIdx.x & 31;
    const int q    = blockIdx.x * 8 + wid;

    float xq[PL];
    #pragma unroll
    for (int i = 0; i < PL; i++) xq[i] = X[q * D + i * 32 + lane];

    float topd[KNN]; int topi[KNN];
    #pragma unroll
    for (int i = 0; i < KNN; i++) { topd[i] = 1e30f; topi[i] = 0; }

    #pragma unroll
    for (int j = 0; j < CAND; j++) {
        const int c = cand[q * CAND + j];
        float dot = 0.0f;
        #pragma unroll
        for (int i = 0; i < PL; i++) dot = fmaf(xq[i], X[c * D + i * 32 + lane], dot);
        #pragma unroll
        for (int o = 16; o > 0; o >>= 1) dot += __shfl_xor_sync(0xFFFFFFFFu, dot, o);
        const float dd = fmaf(-2.0f, dot, sqn[c]);
        if (dd < topd[KNN - 1]) topk_insert(topd, topi, dd, c);
    }
    if (lane == 0) {
        #pragma unroll
        for (int i = 0; i < KNN; i++) outIdx[q * KNN + i] = topi[i];
    }
}

// ---------------- EdgeConv weight split: WP = Wa - Wb, WQ = Wb ----------------
__global__ void prepw_kernel(const float* __restrict__ We, int D)
{
    const int i = blockIdx.x * 256 + threadIdx.x;
    if (i < D * 64) {
        const float b = We[D * 64 + i];
        d_WQ[i] = b;
        d_WP[i] = We[i] - b;
    }
}

// ---------------- EdgeConv aggregation ----------------
__global__ void maxagg_kernel(const float* __restrict__ P, const float* __restrict__ Q,
                              const int* __restrict__ idx, float* __restrict__ g)
{
    const int tid = threadIdx.x;
    const int n = blockIdx.x * 4 + (tid >> 6);
    const int o = tid & 63;
    const float p = P[n * 64 + o];
    float m = -1e30f;
    #pragma unroll
    for (int kk = 0; kk < KNN; kk++) {
        const int j = idx[n * KNN + kk];
        float v = p + Q[j * 64 + o];
        v = (v > 0.0f) ? v : 0.01f * v;
        m = fmaxf(m, v);
    }
    g[n * 64 + o] = m;
}

// ---------------- classifier ----------------
__global__ void classifier_kernel(const float* __restrict__ Wc, const float* __restrict__ bc,
                                  float* __restrict__ out)
{
    const int tid = threadIdx.x;
    const int n = blockIdx.x * 16 + (tid >> 4);
    const int c = tid & 15;
    float acc = bc[c];
    const float* g1r = d_g1 + n * 64;
    const float* g2r = d_g2 + n * 64;
    #pragma unroll 8
    for (int o = 0; o < 64; o++) {
        acc = fmaf(g1r[o], Wc[o * 16 + c], acc);
        acc = fmaf(g2r[o], Wc[(64 + o) * 16 + c], acc);
    }
    out[n * 16 + c] = acc;
}

// ---------------- launch ----------------
extern "C" void kernel_launch(void* const* d_in, const int* in_sizes, int n_in,
                              void* d_out, int out_size)
{
    const float* node_feat = (const float*)d_in[0];
    const float* rf_feat   = (const float*)d_in[1];
    const float* txp_feat  = (const float*)d_in[2];
    const float* Wb  = (const float*)d_in[3];
    const float* bb  = (const float*)d_in[4];
    const float* Wr  = (const float*)d_in[5];
    const float* br  = (const float*)d_in[6];
    const float* Wt  = (const float*)d_in[7];
    const float* bt  = (const float*)d_in[8];
    const float* Wf  = (const float*)d_in[9];
    const float* bf  = (const float*)d_in[10];
    const float* We1 = (const float*)d_in[11];
    const float* be1 = (const float*)d_in[12];
    const float* We2 = (const float*)d_in[13];
    const float* be2 = (const float*)d_in[14];
    const float* Wc  = (const float*)d_in[15];
    const float* bc  = (const float*)d_in[16];
    float* out = (float*)d_out;

    void *pE, *pH, *pg1, *pg2, *pP, *pQ, *psqn, *pidx, *pcand, *pWP, *pWQ;
    cudaGetSymbolAddress(&pE,    d_E);
    cudaGetSymbolAddress(&pH,    d_H);
    cudaGetSymbolAddress(&pg1,   d_g1);
    cudaGetSymbolAddress(&pg2,   d_g2);
    cudaGetSymbolAddress(&pP,    d_P);
    cudaGetSymbolAddress(&pQ,    d_Qm);
    cudaGetSymbolAddress(&psqn,  d_sqn);
    cudaGetSymbolAddress(&pidx,  d_idx);
    cudaGetSymbolAddress(&pcand, d_cand);
    cudaGetSymbolAddress(&pWP,   d_WP);
    cudaGetSymbolAddress(&pWQ,   d_WQ);

    // D=128: 3 tiles x 34816B + fp32 dist 67584B = 172032B dynamic
    // D=64 : 3 tiles x 18432B + fp32 dist 67584B = 122880B dynamic
    const int smem1 = 3 * 128 * 272 + 128 * 132 * 4;
    const int smem2 = 3 * 128 * 144 + 128 * 132 * 4;
    cudaFuncSetAttribute(knn_mma_kernel<128>, cudaFuncAttributeMaxDynamicSharedMemorySize, smem1);
    cudaFuncSetAttribute(knn_mma_kernel<64>,  cudaFuncAttributeMaxDynamicSharedMemorySize, smem2);

    // stage 1: embeds + fusion   (launch order keeps knn<128> at profiled slot #4)
    embed_kernel<<<N_NODES, 192>>>(node_feat, rf_feat, txp_feat, Wb, bb, Wr, br, Wt, bt);
    gemm_kernel<2><<<dim3(N_NODES / 64, 2), 256>>>((const float*)pE, Wf, bf, (float*)pH, 192, 128);

    // EdgeConv 1
    splitsq_kernel<128><<<N_NODES / 8, 256>>>((const float*)pH, (float*)psqn);
    knn_mma_kernel<128><<<128, 512, smem1>>>((const float*)psqn, (int*)pcand);
    rescore_kernel<128><<<N_NODES / 8, 256>>>((const float*)pH, (const float*)psqn,
                                              (const int*)pcand, (int*)pidx);
    prepw_kernel<<<(128 * 64 + 255) / 256, 256>>>(We1, 128);
    gemm_kernel<0><<<dim3(N_NODES / 64, 1), 256>>>((const float*)pH, (const float*)pWP, be1,
                                                   (float*)pP, 128, 64);
    gemm_kernel<0><<<dim3(N_NODES / 64, 1), 256>>>((const float*)pH, (const float*)pWQ, nullptr,
                                                   (float*)pQ, 128, 64);
    maxagg_kernel<<<N_NODES / 4, 256>>>((const float*)pP, (const float*)pQ,
                                        (const int*)pidx, (float*)pg1);

    // EdgeConv 2
    splitsq_kernel<64><<<N_NODES / 8, 256>>>((const float*)pg1, (float*)psqn);
    knn_mma_kernel<64><<<128, 512, smem2>>>((const float*)psqn, (int*)pcand);
    rescore_kernel<64><<<N_NODES / 8, 256>>>((const float*)pg1, (const float*)psqn,
                                             (const int*)pcand, (int*)pidx);
    prepw_kernel<<<(64 * 64 + 255) / 256, 256>>>(We2, 64);
    gemm_kernel<0><<<dim3(N_NODES / 64, 1), 256>>>((const float*)pg1, (const float*)pWP, be2,
                                                   (float*)pP, 64, 64);
    gemm_kernel<0><<<dim3(N_NODES / 64, 1), 256>>>((const float*)pg1, (const float*)pWQ, nullptr,
                                                   (float*)pQ, 64, 64);
    maxagg_kernel<<<N_NODES / 4, 256>>>((const float*)pP, (const float*)pQ,
                                        (const int*)pidx, (float*)pg2);

    // classifier
    classifier_kernel<<<N_NODES / 16, 256>>>(Wc, bc, out);
}

// round 13
// speedup vs baseline: 1.0623x; 1.0238x over previous
#include <cuda_runtime.h>
#include <cuda_bf16.h>
#include <cstdint>

#define N_NODES 16384
#define KNN 10
#define CAND 16   // approx candidates kept per query for exact rescoring

// ---------------- scratch (static device allocations; no runtime alloc) ----------------
__device__ float d_E [N_NODES * 192];
__device__ float d_H [N_NODES * 128];
__device__ float d_g1[N_NODES * 64];
__device__ float d_g2[N_NODES * 64];
__device__ float d_P [N_NODES * 64];
__device__ float d_Qm[N_NODES * 64];
__device__ float d_sqn[N_NODES];
__device__ int   d_idx[N_NODES * KNN];
__device__ int   d_cand[N_NODES * CAND];
__device__ __nv_bfloat16 d_X2[N_NODES * 128];   // bf16(x), up to 128 cols

// ---------------- PTX helpers (generic sm_80+ features only) ----------------
__device__ __forceinline__ uint32_t smem_u32(const void* p) {
    uint32_t a;
    asm("{ .reg .u64 t; cvta.to.shared.u64 t, %1; cvt.u32.u64 %0, t; }" : "=r"(a) : "l"(p));
    return a;
}
#define CP_ASYNC16(dst, src) \
    asm volatile("cp.async.cg.shared.global [%0], [%1], 16;" :: "r"(dst), "l"(src))
#define CP_COMMIT() asm volatile("cp.async.commit_group;" ::: "memory")
#define CP_WAIT0()  asm volatile("cp.async.wait_group 0;" ::: "memory")

#define LDSM4(r0, r1, r2, r3, addr) \
    asm volatile("ldmatrix.sync.aligned.m8n8.x4.shared.b16 {%0,%1,%2,%3}, [%4];" \
                 : "=r"(r0), "=r"(r1), "=r"(r2), "=r"(r3) : "r"(addr))

#define MMA16816(d, a, b) \
    asm volatile("mma.sync.aligned.m16n8k16.row.col.f32.bf16.bf16.f32 " \
                 "{%0,%1,%2,%3}, {%4,%5,%6,%7}, {%8,%9}, {%0,%1,%2,%3};" \
                 : "+f"((d)[0]), "+f"((d)[1]), "+f"((d)[2]), "+f"((d)[3]) \
                 : "r"((a)[0]), "r"((a)[1]), "r"((a)[2]), "r"((a)[3]), \
                   "r"((b)[0]), "r"((b)[1]))

// ---------------- stage 1: per-modality embeds (relu) -> E[N,192] ----------------
__global__ void embed_kernel(const float* __restrict__ nf, const float* __restrict__ rf,
                             const float* __restrict__ tf,
                             const float* __restrict__ Wb, const float* __restrict__ bb,
                             const float* __restrict__ Wr, const float* __restrict__ br,
                             const float* __restrict__ Wt, const float* __restrict__ bt)
{
    __shared__ float s[136];
    const int n = blockIdx.x;
    const int t = threadIdx.x;
    if (t < 8)                 s[t]            = nf[n * 8 + t];
    if (t >= 64 && t < 128)    s[8 + (t - 64)] = rf[n * 64 + (t - 64)];
    if (t >= 128)              s[72 + (t-128)] = tf[n * 64 + (t - 128)];
    __syncthreads();

    float acc;
    if (t < 64) {
        acc = bb[t];
        #pragma unroll
        for (int e = 0; e < 8; e++) acc = fmaf(s[e], Wb[e * 64 + t], acc);
    } else if (t < 128) {
        const int o = t - 64;
        acc = br[o];
        #pragma unroll 8
        for (int e = 0; e < 64; e++) acc = fmaf(s[8 + e], Wr[e * 64 + o], acc);
    } else {
        const int o = t - 128;
        acc = bt[o];
        #pragma unroll 8
        for (int e = 0; e < 64; e++) acc = fmaf(s[72 + e], Wt[e * 64 + o], acc);
    }
    d_E[n * 192 + t] = fmaxf(acc, 0.0f);
}

// ---------------- generic tiled fp32 GEMM (fusion layer) ----------------
template <int ACT>
__global__ __launch_bounds__(256) void gemm_kernel(const float* __restrict__ A,
                                                   const float* __restrict__ W,
                                                   const float* __restrict__ bias,
                                                   float* __restrict__ C,
                                                   int Kd, int Nc)
{
    __shared__ float As[16][64];
    __shared__ float Ws[16][64];
    const int m0 = blockIdx.x * 64;
    const int n0 = blockIdx.y * 64;
    const int tid = threadIdx.x;
    const int tx = tid & 15;
    const int ty = tid >> 4;

    float acc[4][4];
    #pragma unroll
    for (int i = 0; i < 4; i++)
        #pragma unroll
        for (int j = 0; j < 4; j++) acc[i][j] = 0.0f;

    for (int k0 = 0; k0 < Kd; k0 += 16) {
        {
            const int m  = tid >> 2;
            const int kq = (tid & 3) * 4;
            float4 v = *reinterpret_cast<const float4*>(&A[(m0 + m) * Kd + k0 + kq]);
            As[kq + 0][m] = v.x; As[kq + 1][m] = v.y;
            As[kq + 2][m] = v.z; As[kq + 3][m] = v.w;
            const int kk = tid >> 4;
            const int nq = (tid & 15) * 4;
            float4 w = *reinterpret_cast<const float4*>(&W[(k0 + kk) * Nc + n0 + nq]);
            *reinterpret_cast<float4*>(&Ws[kk][nq]) = w;
        }
        __syncthreads();
        #pragma unroll
        for (int k = 0; k < 16; k++) {
            float4 a = *reinterpret_cast<const float4*>(&As[k][ty * 4]);
            float4 b = *reinterpret_cast<const float4*>(&Ws[k][tx * 4]);
            float av[4] = {a.x, a.y, a.z, a.w};
            float bv[4] = {b.x, b.y, b.z, b.w};
            #pragma unroll
            for (int i = 0; i < 4; i++)
                #pragma unroll
                for (int j = 0; j < 4; j++)
                    acc[i][j] = fmaf(av[i], bv[j], acc[i][j]);
        }
        __syncthreads();
    }

    #pragma unroll
    for (int i = 0; i < 4; i++) {
        const int m = m0 + ty * 4 + i;
        #pragma unroll
        for (int j = 0; j < 4; j++) {
            const int n = n0 + tx * 4 + j;
            float v = acc[i][j] + (bias ? bias[n] : 0.0f);
            if (ACT == 2) v = (v > 0.0f) ? v : 0.01f * v;
            C[m * Nc + n] = v;
        }
    }
}

// ---------------- fused P/Q GEMM: y=0 -> P = A@(Wa-Wb)+be, y=1 -> Q = A@Wb ----------
// We layout: [2*Kd, 64] with rows [0,Kd)=Wa, [Kd,2Kd)=Wb. Split folded into W load.
__global__ __launch_bounds__(256) void gemm_pq_kernel(const float* __restrict__ A,
                                                      const float* __restrict__ We,
                                                      const float* __restrict__ be,
                                                      float* __restrict__ P,
                                                      float* __restrict__ Q,
                                                      int Kd)
{
    __shared__ float As[16][64];
    __shared__ float Ws[16][64];
    const int m0 = blockIdx.x * 64;
    const int isQ = blockIdx.y;        // 0 -> P, 1 -> Q
    const int tid = threadIdx.x;
    const int tx = tid & 15;
    const int ty = tid >> 4;

    float acc[4][4];
    #pragma unroll
    for (int i = 0; i < 4; i++)
        #pragma unroll
        for (int j = 0; j < 4; j++) acc[i][j] = 0.0f;

    for (int k0 = 0; k0 < Kd; k0 += 16) {
        {
            const int m  = tid >> 2;
            const int kq = (tid & 3) * 4;
            float4 v = *reinterpret_cast<const float4*>(&A[(m0 + m) * Kd + k0 + kq]);
            As[kq + 0][m] = v.x; As[kq + 1][m] = v.y;
            As[kq + 2][m] = v.z; As[kq + 3][m] = v.w;
            const int kk = tid >> 4;
            const int nq = (tid & 15) * 4;
            float4 wb = *reinterpret_cast<const float4*>(&We[(Kd + k0 + kk) * 64 + nq]);
            if (!isQ) {
                float4 wa = *reinterpret_cast<const float4*>(&We[(k0 + kk) * 64 + nq]);
                wb.x = wa.x - wb.x; wb.y = wa.y - wb.y;
                wb.z = wa.z - wb.z; wb.w = wa.w - wb.w;
            }
            *reinterpret_cast<float4*>(&Ws[kk][nq]) = wb;
        }
        __syncthreads();
        #pragma unroll
        for (int k = 0; k < 16; k++) {
            float4 a = *reinterpret_cast<const float4*>(&As[k][ty * 4]);
            float4 b = *reinterpret_cast<const float4*>(&Ws[k][tx * 4]);
            float av[4] = {a.x, a.y, a.z, a.w};
            float bv[4] = {b.x, b.y, b.z, b.w};
            #pragma unroll
            for (int i = 0; i < 4; i++)
                #pragma unroll
                for (int j = 0; j < 4; j++)
                    acc[i][j] = fmaf(av[i], bv[j], acc[i][j]);
        }
        __syncthreads();
    }

    float* C = isQ ? Q : P;
    #pragma unroll
    for (int i = 0; i < 4; i++) {
        const int m = m0 + ty * 4 + i;
        #pragma unroll
        for (int j = 0; j < 4; j++) {
            const int n = tx * 4 + j;
            float v = acc[i][j] + (isQ ? 0.0f : be[n]);
            C[m * 64 + n] = v;
        }
    }
}

// ---------------- fused: bf16 cast (to d_X2) + exact fp32 squared norms ----------
template <int D>
__global__ void splitsq_kernel(const float* __restrict__ X, float* __restrict__ sqn)
{
    constexpr int PL = D / 32;
    const int wid  = threadIdx.x >> 5;
    const int lane = threadIdx.x & 31;
    const int n    = blockIdx.x * 8 + wid;

    float v[PL];
    if constexpr (PL == 4) {
        float4 t = *reinterpret_cast<const float4*>(&X[n * D + lane * 4]);
        v[0] = t.x; v[1] = t.y; v[2] = t.z; v[3] = t.w;
    } else {
        float2 t = *reinterpret_cast<const float2*>(&X[n * D + lane * 2]);
        v[0] = t.x; v[1] = t.y;
    }

    float s = 0.0f;
    #pragma unroll
    for (int i = 0; i < PL; i++) s = fmaf(v[i], v[i], s);
    #pragma unroll
    for (int o = 16; o > 0; o >>= 1) s += __shfl_xor_sync(0xFFFFFFFFu, s, o);
    if (lane == 0) sqn[n] = s;

    if constexpr (PL == 4) {
        __nv_bfloat162 h0 = __floats2bfloat162_rn(v[0], v[1]);
        __nv_bfloat162 h1 = __floats2bfloat162_rn(v[2], v[3]);
        *reinterpret_cast<__nv_bfloat162*>(&d_X2[n * D + lane * 4])     = h0;
        *reinterpret_cast<__nv_bfloat162*>(&d_X2[n * D + lane * 4 + 2]) = h1;
    } else {
        __nv_bfloat162 h0 = __floats2bfloat162_rn(v[0], v[1]);
        *reinterpret_cast<__nv_bfloat162*>(&d_X2[n * D + lane * 2]) = h0;
    }
}

// ---------------- top-k insert (generic length) ----------------
template <int M>
__device__ __forceinline__ void topk_insert(float (&topd)[M], int (&topi)[M],
                                            float dd, int ci)
{
    topd[M - 1] = dd; topi[M - 1] = ci;
    #pragma unroll
    for (int z = M - 2; z >= 0; z--) {
        if (topd[z] > topd[z + 1]) {
            float td = topd[z]; topd[z] = topd[z + 1]; topd[z + 1] = td;
            int   ti = topi[z]; topi[z] = topi[z + 1]; topi[z + 1] = ti;
        }
    }
}

// ---------------- approx KNN via mma.sync (single-term bf16 Gram), 512 threads ----
// 128 queries/block, 128-candidate tiles, 16 warps; warp = 32q x 32c patch.
// fp32 dist, single buffer; argmin-loop scan (proven R10 configuration).
template <int D>
__global__ __launch_bounds__(512, 1) void knn_mma_kernel(const float* __restrict__ sqn,
                                                         int* __restrict__ outCand)
{
    constexpr int PAD   = 8;
    constexpr int PB    = (D + PAD) * 2;        // tile smem row pitch in bytes
    constexpr int TILEB = 128 * PB;
    constexpr int CH    = D / 8;                // 16B chunks per row

    extern __shared__ char smch[];
    char* qt  = smch;
    char* ct0 = smch + TILEB;
    char* ct1 = smch + 2 * TILEB;
    float* dist = reinterpret_cast<float*>(smch + 3 * TILEB);  // 128*132 floats

    __shared__ float s_sqc[2][128];
    __shared__ float s_mg [128 * CAND];
    __shared__ int   s_mgi[128 * CAND];

    const int tid  = threadIdx.x;
    const int wid  = tid >> 5;
    const int lane = tid & 31;
    const int q0   = blockIdx.x * 128;

    const int mrow = (wid & 3) * 32;            // warp's query-row base
    const int ncol = (wid >> 2) * 32;           // warp's candidate-col base
    const int lrow = lane & 15;
    const int lkof = (lane >> 4) * 16;

    const uint32_t qtu  = smem_u32(qt);
    const uint32_t ctu0 = smem_u32(ct0);
    const uint32_t ctu1 = smem_u32(ct1);
    const uint32_t aBase = qtu + (mrow + lrow) * PB + lkof;
    const uint32_t bOff  = (ncol + lrow) * PB + lkof;

    {
        #pragma unroll
        for (int i = tid; i < 128 * CH; i += 512) {
            const int r  = i / CH;
            const int ch = i - r * CH;
            CP_ASYNC16(qtu + r * PB + ch * 16,
                       d_X2 + (size_t)(q0 + r) * D + ch * 8);
        }
        #pragma unroll
        for (int i = tid; i < 128 * CH; i += 512) {
            const int r  = i / CH;
            const int ch = i - r * CH;
            CP_ASYNC16(ctu0 + r * PB + ch * 16,
                       d_X2 + (size_t)r * D + ch * 8);
        }
        CP_COMMIT();
        if (tid < 128) s_sqc[0][tid] = sqn[tid];
    }

    float topd[CAND]; int topi[CAND];
    #pragma unroll
    for (int i = 0; i < CAND; i++) { topd[i] = 1e30f; topi[i] = 0; }

    const int qmine = tid & 127;     // query owned for scanning
    const int grp   = tid >> 7;      // 0..3: quarter of the candidate tile
    const int cbase = grp * 32;

    // argmin-loop scan of this thread's 32-candidate segment (tile base cp0).
    float* const myrow = &dist[(tid & 127) * 132 + cbase];
    auto scan_row = [&](int cp0) {
        while (true) {
            float bm = 1e30f; int ba = 0;
            #pragma unroll
            for (int cc = 0; cc < 8; cc++) {
                float4 v = *reinterpret_cast<const float4*>(&myrow[cc * 4]);
                if (v.x < bm) { bm = v.x; ba = cc * 4 + 0; }
                if (v.y < bm) { bm = v.y; ba = cc * 4 + 1; }
                if (v.z < bm) { bm = v.z; ba = cc * 4 + 2; }
                if (v.w < bm) { bm = v.w; ba = cc * 4 + 3; }
            }
            if (bm >= topd[CAND - 1]) break;
            topk_insert(topd, topi, bm, cp0 + cbase + ba);
            myrow[ba] = 1e30f;   // remove from pool (thread-exclusive segment)
        }
    };

    const int T = N_NODES / 128;
    for (int t = 0; t < T; t++) {
        CP_WAIT0();
        __syncthreads();   // ct(t) resident; dist(t-1) writes visible

        const uint32_t ctu = (t & 1) ? ctu1 : ctu0;
        if (t + 1 < T) {
            const uint32_t ctn = ((t + 1) & 1) ? ctu1 : ctu0;
            const int r0n = (t + 1) * 128;
            #pragma unroll
            for (int i = tid; i < 128 * CH; i += 512) {
                const int r  = i / CH;
                const int ch = i - r * CH;
                CP_ASYNC16(ctn + r * PB + ch * 16,
                           d_X2 + (size_t)(r0n + r) * D + ch * 8);
            }
            CP_COMMIT();
            if (tid < 128) s_sqc[(t + 1) & 1][tid] = sqn[r0n + tid];
        }

        // ---- Gram: warp 32q x 32c, m16n8k16 atoms ----
        float acc[2][4][4];
        #pragma unroll
        for (int mt = 0; mt < 2; mt++)
            #pragma unroll
            for (int nt = 0; nt < 4; nt++)
                #pragma unroll
                for (int r = 0; r < 4; r++) acc[mt][nt][r] = 0.0f;

        const uint32_t bBase = ctu + bOff;
        #pragma unroll
        for (int kc = 0; kc < D; kc += 16) {
            uint32_t a[2][4];
            #pragma unroll
            for (int mt = 0; mt < 2; mt++)
                LDSM4(a[mt][0], a[mt][1], a[mt][2], a[mt][3],
                      aBase + mt * 16 * PB + kc * 2);
            uint32_t b[4][2];
            #pragma unroll
            for (int nb = 0; nb < 2; nb++) {
                uint32_t r0, r1, r2, r3;
                LDSM4(r0, r1, r2, r3, bBase + nb * 16 * PB + kc * 2);
                b[nb * 2][0] = r0; b[nb * 2][1] = r2;
                b[nb * 2 + 1][0] = r1; b[nb * 2 + 1][1] = r3;
            }
            #pragma unroll
            for (int mt = 0; mt < 2; mt++)
                #pragma unroll
                for (int nt = 0; nt < 4; nt++)
                    MMA16816(acc[mt][nt], a[mt], b[nt]);
        }

        // ---- scan dist(t-1) — independent of MMA(t); fills its latency ----
        if (t > 0) scan_row((t - 1) * 128);
        __syncthreads();   // all scans done before dist rewrite

        // ---- write dist(t), fp32 ----
        const float* sq = s_sqc[t & 1];
        const int c0 = t * 128;

        #pragma unroll
        for (int mt = 0; mt < 2; mt++) {
            const int qA = mrow + mt * 16 + (lane >> 2);
            #pragma unroll
            for (int nt = 0; nt < 4; nt++) {
                const int c = ncol + nt * 8 + (lane & 3) * 2;
                const float s0 = sq[c], s1 = sq[c + 1];
                float2 v0, v1;
                v0.x = fmaf(-2.0f, acc[mt][nt][0], s0);
                v0.y = fmaf(-2.0f, acc[mt][nt][1], s1);
                v1.x = fmaf(-2.0f, acc[mt][nt][2], s0);
                v1.y = fmaf(-2.0f, acc[mt][nt][3], s1);
                const int dq = (q0 + qA) - (c0 + c);
                if (dq ==  0) v0.x = 1e30f;
                if (dq ==  1) v0.y = 1e30f;
                if (dq == -8) v1.x = 1e30f;
                if (dq == -7) v1.y = 1e30f;
                *reinterpret_cast<float2*>(&dist[qA * 132 + c])       = v0;
                *reinterpret_cast<float2*>(&dist[(qA + 8) * 132 + c]) = v1;
            }
        }
    }

    // final tile's scan
    __syncthreads();
    scan_row((T - 1) * 128);

    // ---- merge the four per-query quarters (3 rounds through one buffer) ----
    #pragma unroll 1
    for (int s = 1; s < 4; s++) {
        __syncthreads();
        if (grp == s) {
            #pragma unroll
            for (int i = 0; i < CAND; i++) {
                s_mg [qmine * CAND + i] = topd[i];
                s_mgi[qmine * CAND + i] = topi[i];
            }
        }
        __syncthreads();
        if (grp == 0) {
            #pragma unroll
            for (int i = 0; i < CAND; i++) {
                const float dd = s_mg[qmine * CAND + i];
                if (dd < topd[CAND - 1]) topk_insert(topd, topi, dd, s_mgi[qmine * CAND + i]);
            }
        }
    }
    if (grp == 0) {
        #pragma unroll
        for (int i = 0; i < CAND; i++) outCand[(q0 + qmine) * CAND + i] = topi[i];
    }
}

// ---------------- exact fp32 rescore: top-KNN of CAND candidates per query -------
template <int D>
__global__ void rescore_kernel(const float* __restrict__ X, const float* __restrict__ sqn,
                               const int* __restrict__ cand, int* __restrict__ outIdx)
{
    constexpr int PL = D / 32;
    const int wid  = threadIdx.x >> 5;
    const int lane = threadIdx.x & 31;
    const int q    = blockIdx.x * 8 + wid;

    float xq[PL];
    #pragma unroll
    for (int i = 0; i < PL; i++) xq[i] = X[q * D + i * 32 + lane];

    float topd[KNN]; int topi[KNN];
    #pragma unroll
    for (int i = 0; i < KNN; i++) { topd[i] = 1e30f; topi[i] = 0; }

    #pragma unroll
    for (int j = 0; j < CAND; j++) {
        const int c = cand[q * CAND + j];
        float dot = 0.0f;
        #pragma unroll
        for (int i = 0; i < PL; i++) dot = fmaf(xq[i], X[c * D + i * 32 + lane], dot);
        #pragma unroll
        for (int o = 16; o > 0; o >>= 1) dot += __shfl_xor_sync(0xFFFFFFFFu, dot, o);
        const float dd = fmaf(-2.0f, dot, sqn[c]);
        if (dd < topd[KNN - 1]) topk_insert(topd, topi, dd, c);
    }
    if (lane == 0) {
        #pragma unroll
        for (int i = 0; i < KNN; i++) outIdx[q * KNN + i] = topi[i];
    }
}

// ---------------- EdgeConv aggregation; FUSE_SPLIT also emits bf16 + sqn ---------
template <int FUSE_SPLIT>
__global__ void maxagg_kernel(const float* __restrict__ P, const float* __restrict__ Q,
                              const int* __restrict__ idx, float* __restrict__ g,
                              float* __restrict__ sqn)
{
    __shared__ float s_part[8];
    const int tid = threadIdx.x;
    const int n = blockIdx.x * 4 + (tid >> 6);
    const int o = tid & 63;
    const float p = P[n * 64 + o];
    float m = -1e30f;
    #pragma unroll
    for (int kk = 0; kk < KNN; kk++) {
        const int j = idx[n * KNN + kk];
        float v = p + Q[j * 64 + o];
        v = (v > 0.0f) ? v : 0.01f * v;
        m = fmaxf(m, v);
    }
    g[n * 64 + o] = m;

    if (FUSE_SPLIT) {
        // bf16 cast for the next KNN stage
        d_X2[n * 64 + o] = __float2bfloat16(m);
        // exact fp32 squared norm: reduce m*m over the node's 64 lanes (2 warps)
        float s = m * m;
        #pragma unroll
        for (int off = 16; off > 0; off >>= 1)
            s += __shfl_xor_sync(0xFFFFFFFFu, s, off);
        const int wid = tid >> 5;                 // warp id in block (0..7)
        if ((tid & 31) == 0) s_part[wid] = s;
        __syncthreads();
        if (o == 0) sqn[n] = s_part[(tid >> 6) * 2] + s_part[(tid >> 6) * 2 + 1];
    }
}

// ---------------- classifier ----------------
__global__ void classifier_kernel(const float* __restrict__ Wc, const float* __restrict__ bc,
                                  float* __restrict__ out)
{
    const int tid = threadIdx.x;
    const int n = blockIdx.x * 16 + (tid >> 4);
    const int c = tid & 15;
    float acc = bc[c];
    const float* g1r = d_g1 + n * 64;
    const float* g2r = d_g2 + n * 64;
    #pragma unroll 8
    for (int o = 0; o < 64; o++) {
        acc = fmaf(g1r[o], Wc[o * 16 + c], acc);
        acc = fmaf(g2r[o], Wc[(64 + o) * 16 + c], acc);
    }
    out[n * 16 + c] = acc;
}

// ---------------- launch ----------------
extern "C" void kernel_launch(void* const* d_in, const int* in_sizes, int n_in,
                              void* d_out, int out_size)
{
    const float* node_feat = (const float*)d_in[0];
    const float* rf_feat   = (const float*)d_in[1];
    const float* txp_feat  = (const float*)d_in[2];
    const float* Wb  = (const float*)d_in[3];
    const float* bb  = (const float*)d_in[4];
    const float* Wr  = (const float*)d_in[5];
    const float* br  = (const float*)d_in[6];
    const float* Wt  = (const float*)d_in[7];
    const float* bt  = (const float*)d_in[8];
    const float* Wf  = (const float*)d_in[9];
    const float* bf  = (const float*)d_in[10];
    const float* We1 = (const float*)d_in[11];
    const float* be1 = (const float*)d_in[12];
    const float* We2 = (const float*)d_in[13];
    const float* be2 = (const float*)d_in[14];
    const float* Wc  = (const float*)d_in[15];
    const float* bc  = (const float*)d_in[16];
    float* out = (float*)d_out;

    void *pE, *pH, *pg1, *pg2, *pP, *pQ, *psqn, *pidx, *pcand;
    cudaGetSymbolAddress(&pE,    d_E);
    cudaGetSymbolAddress(&pH,    d_H);
    cudaGetSymbolAddress(&pg1,   d_g1);
    cudaGetSymbolAddress(&pg2,   d_g2);
    cudaGetSymbolAddress(&pP,    d_P);
    cudaGetSymbolAddress(&pQ,    d_Qm);
    cudaGetSymbolAddress(&psqn,  d_sqn);
    cudaGetSymbolAddress(&pidx,  d_idx);
    cudaGetSymbolAddress(&pcand, d_cand);

    // D=128: 3 tiles x 34816B + fp32 dist 67584B = 172032B dynamic
    // D=64 : 3 tiles x 18432B + fp32 dist 67584B = 122880B dynamic
    const int smem1 = 3 * 128 * 272 + 128 * 132 * 4;
    const int smem2 = 3 * 128 * 144 + 128 * 132 * 4;
    cudaFuncSetAttribute(knn_mma_kernel<128>, cudaFuncAttributeMaxDynamicSharedMemorySize, smem1);
    cudaFuncSetAttribute(knn_mma_kernel<64>,  cudaFuncAttributeMaxDynamicSharedMemorySize, smem2);

    // stage 1: embeds + fusion   (launch order keeps knn<128> at profiled slot #4)
    embed_kernel<<<N_NODES, 192>>>(node_feat, rf_feat, txp_feat, Wb, bb, Wr, br, Wt, bt);
    gemm_kernel<2><<<dim3(N_NODES / 64, 2), 256>>>((const float*)pE, Wf, bf, (float*)pH, 192, 128);

    // EdgeConv 1
    splitsq_kernel<128><<<N_NODES / 8, 256>>>((const float*)pH, (float*)psqn);
    knn_mma_kernel<128><<<128, 512, smem1>>>((const float*)psqn, (int*)pcand);
    rescore_kernel<128><<<N_NODES / 8, 256>>>((const float*)pH, (const float*)psqn,
                                              (const int*)pcand, (int*)pidx);
    gemm_pq_kernel<<<dim3(N_NODES / 64, 2), 256>>>((const float*)pH, We1, be1,
                                                   (float*)pP, (float*)pQ, 128);
    // maxagg + fused bf16-split + sqn for the next KNN
    maxagg_kernel<1><<<N_NODES / 4, 256>>>((const float*)pP, (const float*)pQ,
                                           (const int*)pidx, (float*)pg1, (float*)psqn);

    // EdgeConv 2
    knn_mma_kernel<64><<<128, 512, smem2>>>((const float*)psqn, (int*)pcand);
    rescore_kernel<64><<<N_NODES / 8, 256>>>((const float*)pg1, (const float*)psqn,
                                             (const int*)pcand, (int*)pidx);
    gemm_pq_kernel<<<dim3(N_NODES / 64, 2), 256>>>((const float*)pg1, We2, be2,
                                                   (float*)pP, (float*)pQ, 64);
    maxagg_kernel<0><<<N_NODES / 4, 256>>>((const float*)pP, (const float*)pQ,
                                           (const int*)pidx, (float*)pg2, nullptr);

    // classifier
    classifier_kernel<<<N_NODES / 16, 256>>>(Wc, bc, out);
}

// round 14
// speedup vs baseline: 1.0648x; 1.0023x over previous
#include <cuda_runtime.h>
#include <cuda_bf16.h>
#include <cstdint>

#define N_NODES 16384
#define KNN 10
#define CAND 16   // approx candidates kept per query for exact rescoring

// ---------------- scratch (static device allocations; no runtime alloc) ----------------
__device__ float d_E [N_NODES * 192];
__device__ float d_H [N_NODES * 128];
__device__ float d_g1[N_NODES * 64];
__device__ float d_g2[N_NODES * 64];
__device__ float d_P [N_NODES * 64];
__device__ float d_Qm[N_NODES * 64];
__device__ float d_sqA[N_NODES];
__device__ float d_sqB[N_NODES];
__device__ float d_sqn2[N_NODES];
__device__ int   d_cand[N_NODES * CAND];
__device__ __nv_bfloat16 d_X2[N_NODES * 128];   // bf16(x), up to 128 cols

// ---------------- PTX helpers (generic sm_80+ features only) ----------------
__device__ __forceinline__ uint32_t smem_u32(const void* p) {
    uint32_t a;
    asm("{ .reg .u64 t; cvta.to.shared.u64 t, %1; cvt.u32.u64 %0, t; }" : "=r"(a) : "l"(p));
    return a;
}
#define CP_ASYNC16(dst, src) \
    asm volatile("cp.async.cg.shared.global [%0], [%1], 16;" :: "r"(dst), "l"(src))
#define CP_COMMIT() asm volatile("cp.async.commit_group;" ::: "memory")
#define CP_WAIT0()  asm volatile("cp.async.wait_group 0;" ::: "memory")

#define LDSM4(r0, r1, r2, r3, addr) \
    asm volatile("ldmatrix.sync.aligned.m8n8.x4.shared.b16 {%0,%1,%2,%3}, [%4];" \
                 : "=r"(r0), "=r"(r1), "=r"(r2), "=r"(r3) : "r"(addr))

#define MMA16816(d, a, b) \
    asm volatile("mma.sync.aligned.m16n8k16.row.col.f32.bf16.bf16.f32 " \
                 "{%0,%1,%2,%3}, {%4,%5,%6,%7}, {%8,%9}, {%0,%1,%2,%3};" \
                 : "+f"((d)[0]), "+f"((d)[1]), "+f"((d)[2]), "+f"((d)[3]) \
                 : "r"((a)[0]), "r"((a)[1]), "r"((a)[2]), "r"((a)[3]), \
                   "r"((b)[0]), "r"((b)[1]))

// ---------------- stage 1: per-modality embeds (relu) -> E[N,192] ----------------
__global__ void embed_kernel(const float* __restrict__ nf, const float* __restrict__ rf,
                             const float* __restrict__ tf,
                             const float* __restrict__ Wb, const float* __restrict__ bb,
                             const float* __restrict__ Wr, const float* __restrict__ br,
                             const float* __restrict__ Wt, const float* __restrict__ bt)
{
    __shared__ float s[136];
    const int n = blockIdx.x;
    const int t = threadIdx.x;
    if (t < 8)                 s[t]            = nf[n * 8 + t];
    if (t >= 64 && t < 128)    s[8 + (t - 64)] = rf[n * 64 + (t - 64)];
    if (t >= 128)              s[72 + (t-128)] = tf[n * 64 + (t - 128)];
    __syncthreads();

    float acc;
    if (t < 64) {
        acc = bb[t];
        #pragma unroll
        for (int e = 0; e < 8; e++) acc = fmaf(s[e], Wb[e * 64 + t], acc);
    } else if (t < 128) {
        const int o = t - 64;
        acc = br[o];
        #pragma unroll 8
        for (int e = 0; e < 64; e++) acc = fmaf(s[8 + e], Wr[e * 64 + o], acc);
    } else {
        const int o = t - 128;
        acc = bt[o];
        #pragma unroll 8
        for (int e = 0; e < 64; e++) acc = fmaf(s[72 + e], Wt[e * 64 + o], acc);
    }
    d_E[n * 192 + t] = fmaxf(acc, 0.0f);
}

// ---------------- fusion GEMM: H = leaky(E@Wf+bf); EMIT: also bf16->d_X2 and
// per-row partial sq-norms into d_sqA (cols 0..63) / d_sqB (cols 64..127) -------
template <int ACT, int EMIT>
__global__ __launch_bounds__(256) void gemm_kernel(const float* __restrict__ A,
                                                   const float* __restrict__ W,
                                                   const float* __restrict__ bias,
                                                   float* __restrict__ C,
                                                   int Kd, int Nc)
{
    __shared__ float As[16][64];
    __shared__ float Ws[16][64];
    const int m0 = blockIdx.x * 64;
    const int n0 = blockIdx.y * 64;
    const int tid = threadIdx.x;
    const int tx = tid & 15;
    const int ty = tid >> 4;

    float acc[4][4];
    #pragma unroll
    for (int i = 0; i < 4; i++)
        #pragma unroll
        for (int j = 0; j < 4; j++) acc[i][j] = 0.0f;

    for (int k0 = 0; k0 < Kd; k0 += 16) {
        {
            const int m  = tid >> 2;
            const int kq = (tid & 3) * 4;
            float4 v = *reinterpret_cast<const float4*>(&A[(m0 + m) * Kd + k0 + kq]);
            As[kq + 0][m] = v.x; As[kq + 1][m] = v.y;
            As[kq + 2][m] = v.z; As[kq + 3][m] = v.w;
            const int kk = tid >> 4;
            const int nq = (tid & 15) * 4;
            float4 w = *reinterpret_cast<const float4*>(&W[(k0 + kk) * Nc + n0 + nq]);
            *reinterpret_cast<float4*>(&Ws[kk][nq]) = w;
        }
        __syncthreads();
        #pragma unroll
        for (int k = 0; k < 16; k++) {
            float4 a = *reinterpret_cast<const float4*>(&As[k][ty * 4]);
            float4 b = *reinterpret_cast<const float4*>(&Ws[k][tx * 4]);
            float av[4] = {a.x, a.y, a.z, a.w};
            float bv[4] = {b.x, b.y, b.z, b.w};
            #pragma unroll
            for (int i = 0; i < 4; i++)
                #pragma unroll
                for (int j = 0; j < 4; j++)
                    acc[i][j] = fmaf(av[i], bv[j], acc[i][j]);
        }
        __syncthreads();
    }

    #pragma unroll
    for (int i = 0; i < 4; i++) {
        const int m = m0 + ty * 4 + i;
        float ss = 0.0f;
        #pragma unroll
        for (int j = 0; j < 4; j++) {
            const int n = n0 + tx * 4 + j;
            float v = acc[i][j] + (bias ? bias[n] : 0.0f);
            if (ACT == 2) v = (v > 0.0f) ? v : 0.01f * v;
            C[m * Nc + n] = v;
            if (EMIT) {
                d_X2[m * 128 + n] = __float2bfloat16(v);
                ss = fmaf(v, v, ss);
            }
        }
        if (EMIT) {
            // reduce over the 16 tx-lanes covering this row's 64-col half
            #pragma unroll
            for (int o = 8; o > 0; o >>= 1)
                ss += __shfl_xor_sync(0xFFFFFFFFu, ss, o);
            if (tx == 0) {
                if (n0 == 0) d_sqA[m] = ss; else d_sqB[m] = ss;
            }
        }
    }
}

// ---------------- fused P/Q GEMM: y=0 -> P = A@(Wa-Wb)+be, y=1 -> Q = A@Wb ----------
__global__ __launch_bounds__(256) void gemm_pq_kernel(const float* __restrict__ A,
                                                      const float* __restrict__ We,
                                                      const float* __restrict__ be,
                                                      float* __restrict__ P,
                                                      float* __restrict__ Q,
                                                      int Kd)
{
    __shared__ float As[16][64];
    __shared__ float Ws[16][64];
    const int m0 = blockIdx.x * 64;
    const int isQ = blockIdx.y;        // 0 -> P, 1 -> Q
    const int tid = threadIdx.x;
    const int tx = tid & 15;
    const int ty = tid >> 4;

    float acc[4][4];
    #pragma unroll
    for (int i = 0; i < 4; i++)
        #pragma unroll
        for (int j = 0; j < 4; j++) acc[i][j] = 0.0f;

    for (int k0 = 0; k0 < Kd; k0 += 16) {
        {
            const int m  = tid >> 2;
            const int kq = (tid & 3) * 4;
            float4 v = *reinterpret_cast<const float4*>(&A[(m0 + m) * Kd + k0 + kq]);
            As[kq + 0][m] = v.x; As[kq + 1][m] = v.y;
            As[kq + 2][m] = v.z; As[kq + 3][m] = v.w;
            const int kk = tid >> 4;
            const int nq = (tid & 15) * 4;
            float4 wb = *reinterpret_cast<const float4*>(&We[(Kd + k0 + kk) * 64 + nq]);
            if (!isQ) {
                float4 wa = *reinterpret_cast<const float4*>(&We[(k0 + kk) * 64 + nq]);
                wb.x = wa.x - wb.x; wb.y = wa.y - wb.y;
                wb.z = wa.z - wb.z; wb.w = wa.w - wb.w;
            }
            *reinterpret_cast<float4*>(&Ws[kk][nq]) = wb;
        }
        __syncthreads();
        #pragma unroll
        for (int k = 0; k < 16; k++) {
            float4 a = *reinterpret_cast<const float4*>(&As[k][ty * 4]);
            float4 b = *reinterpret_cast<const float4*>(&Ws[k][tx * 4]);
            float av[4] = {a.x, a.y, a.z, a.w};
            float bv[4] = {b.x, b.y, b.z, b.w};
            #pragma unroll
            for (int i = 0; i < 4; i++)
                #pragma unroll
                for (int j = 0; j < 4; j++)
                    acc[i][j] = fmaf(av[i], bv[j], acc[i][j]);
        }
        __syncthreads();
    }

    float* C = isQ ? Q : P;
    #pragma unroll
    for (int i = 0; i < 4; i++) {
        const int m = m0 + ty * 4 + i;
        #pragma unroll
        for (int j = 0; j < 4; j++) {
            const int n = tx * 4 + j;
            float v = acc[i][j] + (isQ ? 0.0f : be[n]);
            C[m * 64 + n] = v;
        }
    }
}

// ---------------- top-k insert (generic length) ----------------
template <int M>
__device__ __forceinline__ void topk_insert(float (&topd)[M], int (&topi)[M],
                                            float dd, int ci)
{
    topd[M - 1] = dd; topi[M - 1] = ci;
    #pragma unroll
    for (int z = M - 2; z >= 0; z--) {
        if (topd[z] > topd[z + 1]) {
            float td = topd[z]; topd[z] = topd[z + 1]; topd[z + 1] = td;
            int   ti = topi[z]; topi[z] = topi[z + 1]; topi[z + 1] = ti;
        }
    }
}

// ---------------- approx KNN via mma.sync (single-term bf16 Gram), 512 threads ----
// 128 queries/block, 128-candidate tiles, 16 warps; warp = 32q x 32c patch.
// fp32 dist, single buffer; argmin-loop scan (proven R10 configuration).
// sqn = sqA[c] (+ sqB[c] when provided).
template <int D>
__global__ __launch_bounds__(512, 1) void knn_mma_kernel(const float* __restrict__ sqA,
                                                         const float* __restrict__ sqB,
                                                         int* __restrict__ outCand)
{
    constexpr int PAD   = 8;
    constexpr int PB    = (D + PAD) * 2;        // tile smem row pitch in bytes
    constexpr int TILEB = 128 * PB;
    constexpr int CH    = D / 8;                // 16B chunks per row

    extern __shared__ char smch[];
    char* qt  = smch;
    char* ct0 = smch + TILEB;
    char* ct1 = smch + 2 * TILEB;
    float* dist = reinterpret_cast<float*>(smch + 3 * TILEB);  // 128*132 floats

    __shared__ float s_sqc[2][128];
    __shared__ float s_mg [128 * CAND];
    __shared__ int   s_mgi[128 * CAND];

    const int tid  = threadIdx.x;
    const int wid  = tid >> 5;
    const int lane = tid & 31;
    const int q0   = blockIdx.x * 128;

    const int mrow = (wid & 3) * 32;            // warp's query-row base
    const int ncol = (wid >> 2) * 32;           // warp's candidate-col base
    const int lrow = lane & 15;
    const int lkof = (lane >> 4) * 16;

    const uint32_t qtu  = smem_u32(qt);
    const uint32_t ctu0 = smem_u32(ct0);
    const uint32_t ctu1 = smem_u32(ct1);
    const uint32_t aBase = qtu + (mrow + lrow) * PB + lkof;
    const uint32_t bOff  = (ncol + lrow) * PB + lkof;

    {
        #pragma unroll
        for (int i = tid; i < 128 * CH; i += 512) {
            const int r  = i / CH;
            const int ch = i - r * CH;
            CP_ASYNC16(qtu + r * PB + ch * 16,
                       d_X2 + (size_t)(q0 + r) * D + ch * 8);
        }
        #pragma unroll
        for (int i = tid; i < 128 * CH; i += 512) {
            const int r  = i / CH;
            const int ch = i - r * CH;
            CP_ASYNC16(ctu0 + r * PB + ch * 16,
                       d_X2 + (size_t)r * D + ch * 8);
        }
        CP_COMMIT();
        if (tid < 128) {
            float s = sqA[tid];
            if (sqB) s += sqB[tid];
            s_sqc[0][tid] = s;
        }
    }

    float topd[CAND]; int topi[CAND];
    #pragma unroll
    for (int i = 0; i < CAND; i++) { topd[i] = 1e30f; topi[i] = 0; }

    const int qmine = tid & 127;     // query owned for scanning
    const int grp   = tid >> 7;      // 0..3: quarter of the candidate tile
    const int cbase = grp * 32;

    // argmin-loop scan of this thread's 32-candidate segment (tile base cp0).
    float* const myrow = &dist[(tid & 127) * 132 + cbase];
    auto scan_row = [&](int cp0) {
        while (true) {
            float bm = 1e30f; int ba = 0;
            #pragma unroll
            for (int cc = 0; cc < 8; cc++) {
                float4 v = *reinterpret_cast<const float4*>(&myrow[cc * 4]);
                if (v.x < bm) { bm = v.x; ba = cc * 4 + 0; }
                if (v.y < bm) { bm = v.y; ba = cc * 4 + 1; }
                if (v.z < bm) { bm = v.z; ba = cc * 4 + 2; }
                if (v.w < bm) { bm = v.w; ba = cc * 4 + 3; }
            }
            if (bm >= topd[CAND - 1]) break;
            topk_insert(topd, topi, bm, cp0 + cbase + ba);
            myrow[ba] = 1e30f;   // remove from pool (thread-exclusive segment)
        }
    };

    const int T = N_NODES / 128;
    for (int t = 0; t < T; t++) {
        CP_WAIT0();
        __syncthreads();   // ct(t) resident; dist(t-1) writes visible

        const uint32_t ctu = (t & 1) ? ctu1 : ctu0;
        if (t + 1 < T) {
            const uint32_t ctn = ((t + 1) & 1) ? ctu1 : ctu0;
            const int r0n = (t + 1) * 128;
            #pragma unroll
            for (int i = tid; i < 128 * CH; i += 512) {
                const int r  = i / CH;
                const int ch = i - r * CH;
                CP_ASYNC16(ctn + r * PB + ch * 16,
                           d_X2 + (size_t)(r0n + r) * D + ch * 8);
            }
            CP_COMMIT();
            if (tid < 128) {
                float s = sqA[r0n + tid];
                if (sqB) s += sqB[r0n + tid];
                s_sqc[(t + 1) & 1][tid] = s;
            }
        }

        // ---- Gram: warp 32q x 32c, m16n8k16 atoms ----
        float acc[2][4][4];
        #pragma unroll
        for (int mt = 0; mt < 2; mt++)
            #pragma unroll
            for (int nt = 0; nt < 4; nt++)
                #pragma unroll
                for (int r = 0; r < 4; r++) acc[mt][nt][r] = 0.0f;

        const uint32_t bBase = ctu + bOff;
        #pragma unroll
        for (int kc = 0; kc < D; kc += 16) {
            uint32_t a[2][4];
            #pragma unroll
            for (int mt = 0; mt < 2; mt++)
                LDSM4(a[mt][0], a[mt][1], a[mt][2], a[mt][3],
                      aBase + mt * 16 * PB + kc * 2);
            uint32_t b[4][2];
            #pragma unroll
            for (int nb = 0; nb < 2; nb++) {
                uint32_t r0, r1, r2, r3;
                LDSM4(r0, r1, r2, r3, bBase + nb * 16 * PB + kc * 2);
                b[nb * 2][0] = r0; b[nb * 2][1] = r2;
                b[nb * 2 + 1][0] = r1; b[nb * 2 + 1][1] = r3;
            }
            #pragma unroll
            for (int mt = 0; mt < 2; mt++)
                #pragma unroll
                for (int nt = 0; nt < 4; nt++)
                    MMA16816(acc[mt][nt], a[mt], b[nt]);
        }

        // ---- scan dist(t-1) — independent of MMA(t); fills its latency ----
        if (t > 0) scan_row((t - 1) * 128);
        __syncthreads();   // all scans done before dist rewrite

        // ---- write dist(t), fp32 ----
        const float* sq = s_sqc[t & 1];
        const int c0 = t * 128;

        #pragma unroll
        for (int mt = 0; mt < 2; mt++) {
            const int qA = mrow + mt * 16 + (lane >> 2);
            #pragma unroll
            for (int nt = 0; nt < 4; nt++) {
                const int c = ncol + nt * 8 + (lane & 3) * 2;
                const float s0 = sq[c], s1 = sq[c + 1];
                float2 v0, v1;
                v0.x = fmaf(-2.0f, acc[mt][nt][0], s0);
                v0.y = fmaf(-2.0f, acc[mt][nt][1], s1);
                v1.x = fmaf(-2.0f, acc[mt][nt][2], s0);
                v1.y = fmaf(-2.0f, acc[mt][nt][3], s1);
                const int dq = (q0 + qA) - (c0 + c);
                if (dq ==  0) v0.x = 1e30f;
                if (dq ==  1) v0.y = 1e30f;
                if (dq == -8) v1.x = 1e30f;
                if (dq == -7) v1.y = 1e30f;
                *reinterpret_cast<float2*>(&dist[qA * 132 + c])       = v0;
                *reinterpret_cast<float2*>(&dist[(qA + 8) * 132 + c]) = v1;
            }
        }
    }

    // final tile's scan
    __syncthreads();
    scan_row((T - 1) * 128);

    // ---- merge the four per-query quarters (3 rounds through one buffer) ----
    #pragma unroll 1
    for (int s = 1; s < 4; s++) {
        __syncthreads();
        if (grp == s) {
            #pragma unroll
            for (int i = 0; i < CAND; i++) {
                s_mg [qmine * CAND + i] = topd[i];
                s_mgi[qmine * CAND + i] = topi[i];
            }
        }
        __syncthreads();
        if (grp == 0) {
            #pragma unroll
            for (int i = 0; i < CAND; i++) {
                const float dd = s_mg[qmine * CAND + i];
                if (dd < topd[CAND - 1]) topk_insert(topd, topi, dd, s_mgi[qmine * CAND + i]);
            }
        }
    }
    if (grp == 0) {
        #pragma unroll
        for (int i = 0; i < CAND; i++) outCand[(q0 + qmine) * CAND + i] = topi[i];
    }
}

// ---------------- fused rescore + EdgeConv aggregation ----------------
// One warp per query: exact fp32 rescore of CAND candidates -> top-KNN (all lanes
// hold the result), then max-aggregation g[q,:] = max_k leaky(P[q,:]+Q[idx_k,:]).
// FUSE: also emit bf16(g) -> d_X2 and exact sq-norm -> sqnOut for the next KNN.
template <int D, int FUSE>
__global__ void rescoreagg_kernel(const float* __restrict__ X,
                                  const float* __restrict__ sqA,
                                  const float* __restrict__ sqB,
                                  const int* __restrict__ cand,
                                  const float* __restrict__ P,
                                  const float* __restrict__ Q,
                                  float* __restrict__ g,
                                  float* __restrict__ sqnOut)
{
    constexpr int PL = D / 32;
    const int wid  = threadIdx.x >> 5;
    const int lane = threadIdx.x & 31;
    const int q    = blockIdx.x * 8 + wid;

    float xq[PL];
    #pragma unroll
    for (int i = 0; i < PL; i++) xq[i] = X[q * D + i * 32 + lane];

    float topd[KNN]; int topi[KNN];
    #pragma unroll
    for (int i = 0; i < KNN; i++) { topd[i] = 1e30f; topi[i] = 0; }

    #pragma unroll
    for (int j = 0; j < CAND; j++) {
        const int c = cand[q * CAND + j];
        float dot = 0.0f;
        #pragma unroll
        for (int i = 0; i < PL; i++) dot = fmaf(xq[i], X[c * D + i * 32 + lane], dot);
        #pragma unroll
        for (int o = 16; o > 0; o >>= 1) dot += __shfl_xor_sync(0xFFFFFFFFu, dot, o);
        float sc = sqA[c];
        if (sqB) sc += sqB[c];
        const float dd = fmaf(-2.0f, dot, sc);
        if (dd < topd[KNN - 1]) topk_insert(topd, topi, dd, c);
    }

    // ---- aggregation: every lane holds the full top-KNN index list ----
    const float p0 = P[q * 64 + lane];
    const float p1 = P[q * 64 + 32 + lane];
    float m0 = -1e30f, m1 = -1e30f;
    #pragma unroll
    for (int kk = 0; kk < KNN; kk++) {
        const int j = topi[kk];
        float v0 = p0 + Q[j * 64 + lane];
        float v1 = p1 + Q[j * 64 + 32 + lane];
        v0 = (v0 > 0.0f) ? v0 : 0.01f * v0;
        v1 = (v1 > 0.0f) ? v1 : 0.01f * v1;
        m0 = fmaxf(m0, v0);
        m1 = fmaxf(m1, v1);
    }
    g[q * 64 + lane]      = m0;
    g[q * 64 + 32 + lane] = m1;

    if (FUSE) {
        d_X2[q * 64 + lane]      = __float2bfloat16(m0);
        d_X2[q * 64 + 32 + lane] = __float2bfloat16(m1);
        float s = fmaf(m0, m0, m1 * m1);
        #pragma unroll
        for (int o = 16; o > 0; o >>= 1) s += __shfl_xor_sync(0xFFFFFFFFu, s, o);
        if (lane == 0) sqnOut[q] = s;
    }
}

// ---------------- classifier ----------------
__global__ void classifier_kernel(const float* __restrict__ Wc, const float* __restrict__ bc,
                                  float* __restrict__ out)
{
    const int tid = threadIdx.x;
    const int n = blockIdx.x * 16 + (tid >> 4);
    const int c = tid & 15;
    float acc = bc[c];
    const float* g1r = d_g1 + n * 64;
    const float* g2r = d_g2 + n * 64;
    #pragma unroll 8
    for (int o = 0; o < 64; o++) {
        acc = fmaf(g1r[o], Wc[o * 16 + c], acc);
        acc = fmaf(g2r[o], Wc[(64 + o) * 16 + c], acc);
    }
    out[n * 16 + c] = acc;
}

// ---------------- launch ----------------
extern "C" void kernel_launch(void* const* d_in, const int* in_sizes, int n_in,
                              void* d_out, int out_size)
{
    const float* node_feat = (const float*)d_in[0];
    const float* rf_feat   = (const float*)d_in[1];
    const float* txp_feat  = (const float*)d_in[2];
    const float* Wb  = (const float*)d_in[3];
    const float* bb  = (const float*)d_in[4];
    const float* Wr  = (const float*)d_in[5];
    const float* br  = (const float*)d_in[6];
    const float* Wt  = (const float*)d_in[7];
    const float* bt  = (const float*)d_in[8];
    const float* Wf  = (const float*)d_in[9];
    const float* bf  = (const float*)d_in[10];
    const float* We1 = (const float*)d_in[11];
    const float* be1 = (const float*)d_in[12];
    const float* We2 = (const float*)d_in[13];
    const float* be2 = (const float*)d_in[14];
    const float* Wc  = (const float*)d_in[15];
    const float* bc  = (const float*)d_in[16];
    float* out = (float*)d_out;

    void *pE, *pH, *pg1, *pg2, *pP, *pQ, *psqA, *psqB, *psq2, *pcand;
    cudaGetSymbolAddress(&pE,    d_E);
    cudaGetSymbolAddress(&pH,    d_H);
    cudaGetSymbolAddress(&pg1,   d_g1);
    cudaGetSymbolAddress(&pg2,   d_g2);
    cudaGetSymbolAddress(&pP,    d_P);
    cudaGetSymbolAddress(&pQ,    d_Qm);
    cudaGetSymbolAddress(&psqA,  d_sqA);
    cudaGetSymbolAddress(&psqB,  d_sqB);
    cudaGetSymbolAddress(&psq2,  d_sqn2);
    cudaGetSymbolAddress(&pcand, d_cand);

    // D=128: 3 tiles x 34816B + fp32 dist 67584B = 172032B dynamic
    // D=64 : 3 tiles x 18432B + fp32 dist 67584B = 122880B dynamic
    const int smem1 = 3 * 128 * 272 + 128 * 132 * 4;
    const int smem2 = 3 * 128 * 144 + 128 * 132 * 4;
    cudaFuncSetAttribute(knn_mma_kernel<128>, cudaFuncAttributeMaxDynamicSharedMemorySize, smem1);
    cudaFuncSetAttribute(knn_mma_kernel<64>,  cudaFuncAttributeMaxDynamicSharedMemorySize, smem2);

    // stage 1: embeds + fusion (emits H, bf16 X2, partial sq-norms)
    embed_kernel<<<N_NODES, 192>>>(node_feat, rf_feat, txp_feat, Wb, bb, Wr, br, Wt, bt);
    gemm_kernel<2, 1><<<dim3(N_NODES / 64, 2), 256>>>((const float*)pE, Wf, bf,
                                                      (float*)pH, 192, 128);

    // EdgeConv 1  (gemm_pq before knn keeps knn<128> at profiled slot #4)
    gemm_pq_kernel<<<dim3(N_NODES / 64, 2), 256>>>((const float*)pH, We1, be1,
                                                   (float*)pP, (float*)pQ, 128);
    knn_mma_kernel<128><<<128, 512, smem1>>>((const float*)psqA, (const float*)psqB,
                                             (int*)pcand);
    rescoreagg_kernel<128, 1><<<N_NODES / 8, 256>>>((const float*)pH,
                                                    (const float*)psqA, (const float*)psqB,
                                                    (const int*)pcand,
                                                    (const float*)pP, (const float*)pQ,
                                                    (float*)pg1, (float*)psq2);

    // EdgeConv 2
    gemm_pq_kernel<<<dim3(N_NODES / 64, 2), 256>>>((const float*)pg1, We2, be2,
                                                   (float*)pP, (float*)pQ, 64);
    knn_mma_kernel<64><<<128, 512, smem2>>>((const float*)psq2, nullptr, (int*)pcand);
    rescoreagg_kernel<64, 0><<<N_NODES / 8, 256>>>((const float*)pg1,
                                                   (const float*)psq2, nullptr,
                                                   (const int*)pcand,
                                                   (const float*)pP, (const float*)pQ,
                                                   (float*)pg2, nullptr);

    // classifier
    classifier_kernel<<<N_NODES / 16, 256>>>(Wc, bc, out);
}

// round 15
// speedup vs baseline: 1.0666x; 1.0017x over previous
#include <cuda_runtime.h>
#include <cuda_bf16.h>
#include <cstdint>

#define N_NODES 16384
#define KNN 10
#define CAND 16   // approx candidates kept per query for exact rescoring

// ---------------- scratch (static device allocations; no runtime alloc) ----------------
__device__ float d_E [N_NODES * 192];
__device__ float d_H [N_NODES * 128];
__device__ float d_g1[N_NODES * 64];
__device__ float d_g2[N_NODES * 64];
__device__ float d_P [N_NODES * 64];
__device__ float d_Qm[N_NODES * 64];
__device__ float d_sqA[N_NODES];
__device__ float d_sqB[N_NODES];
__device__ float d_sqn2[N_NODES];
__device__ int   d_cand[N_NODES * CAND];
__device__ __nv_bfloat16 d_X2[N_NODES * 128];   // bf16(x), up to 128 cols

// ---------------- PTX helpers (generic sm_80+ features only) ----------------
__device__ __forceinline__ uint32_t smem_u32(const void* p) {
    uint32_t a;
    asm("{ .reg .u64 t; cvta.to.shared.u64 t, %1; cvt.u32.u64 %0, t; }" : "=r"(a) : "l"(p));
    return a;
}
#define CP_ASYNC16(dst, src) \
    asm volatile("cp.async.cg.shared.global [%0], [%1], 16;" :: "r"(dst), "l"(src))
#define CP_COMMIT() asm volatile("cp.async.commit_group;" ::: "memory")
#define CP_WAIT0()  asm volatile("cp.async.wait_group 0;" ::: "memory")

#define LDSM4(r0, r1, r2, r3, addr) \
    asm volatile("ldmatrix.sync.aligned.m8n8.x4.shared.b16 {%0,%1,%2,%3}, [%4];" \
                 : "=r"(r0), "=r"(r1), "=r"(r2), "=r"(r3) : "r"(addr))

#define MMA16816(d, a, b) \
    asm volatile("mma.sync.aligned.m16n8k16.row.col.f32.bf16.bf16.f32 " \
                 "{%0,%1,%2,%3}, {%4,%5,%6,%7}, {%8,%9}, {%0,%1,%2,%3};" \
                 : "+f"((d)[0]), "+f"((d)[1]), "+f"((d)[2]), "+f"((d)[3]) \
                 : "r"((a)[0]), "r"((a)[1]), "r"((a)[2]), "r"((a)[3]), \
                   "r"((b)[0]), "r"((b)[1]))

// ---------------- stage 1: per-modality embeds (relu) -> E[N,192] ----------------
__global__ void embed_kernel(const float* __restrict__ nf, const float* __restrict__ rf,
                             const float* __restrict__ tf,
                             const float* __restrict__ Wb, const float* __restrict__ bb,
                             const float* __restrict__ Wr, const float* __restrict__ br,
                             const float* __restrict__ Wt, const float* __restrict__ bt)
{
    __shared__ float s[136];
    const int n = blockIdx.x;
    const int t = threadIdx.x;
    if (t < 8)                 s[t]            = nf[n * 8 + t];
    if (t >= 64 && t < 128)    s[8 + (t - 64)] = rf[n * 64 + (t - 64)];
    if (t >= 128)              s[72 + (t-128)] = tf[n * 64 + (t - 128)];
    __syncthreads();

    float acc;
    if (t < 64) {
        acc = bb[t];
        #pragma unroll
        for (int e = 0; e < 8; e++) acc = fmaf(s[e], Wb[e * 64 + t], acc);
    } else if (t < 128) {
        const int o = t - 64;
        acc = br[o];
        #pragma unroll 8
        for (int e = 0; e < 64; e++) acc = fmaf(s[8 + e], Wr[e * 64 + o], acc);
    } else {
        const int o = t - 128;
        acc = bt[o];
        #pragma unroll 8
        for (int e = 0; e < 64; e++) acc = fmaf(s[72 + e], Wt[e * 64 + o], acc);
    }
    d_E[n * 192 + t] = fmaxf(acc, 0.0f);
}

// ---------------- fusion GEMM: H = leaky(E@Wf+bf); EMIT: also bf16->d_X2 and
// per-row partial sq-norms into d_sqA (cols 0..63) / d_sqB (cols 64..127) -------
template <int ACT, int EMIT>
__global__ __launch_bounds__(256) void gemm_kernel(const float* __restrict__ A,
                                                   const float* __restrict__ W,
                                                   const float* __restrict__ bias,
                                                   float* __restrict__ C,
                                                   int Kd, int Nc)
{
    __shared__ float As[16][64];
    __shared__ float Ws[16][64];
    const int m0 = blockIdx.x * 64;
    const int n0 = blockIdx.y * 64;
    const int tid = threadIdx.x;
    const int tx = tid & 15;
    const int ty = tid >> 4;

    float acc[4][4];
    #pragma unroll
    for (int i = 0; i < 4; i++)
        #pragma unroll
        for (int j = 0; j < 4; j++) acc[i][j] = 0.0f;

    for (int k0 = 0; k0 < Kd; k0 += 16) {
        {
            const int m  = tid >> 2;
            const int kq = (tid & 3) * 4;
            float4 v = *reinterpret_cast<const float4*>(&A[(m0 + m) * Kd + k0 + kq]);
            As[kq + 0][m] = v.x; As[kq + 1][m] = v.y;
            As[kq + 2][m] = v.z; As[kq + 3][m] = v.w;
            const int kk = tid >> 4;
            const int nq = (tid & 15) * 4;
            float4 w = *reinterpret_cast<const float4*>(&W[(k0 + kk) * Nc + n0 + nq]);
            *reinterpret_cast<float4*>(&Ws[kk][nq]) = w;
        }
        __syncthreads();
        #pragma unroll
        for (int k = 0; k < 16; k++) {
            float4 a = *reinterpret_cast<const float4*>(&As[k][ty * 4]);
            float4 b = *reinterpret_cast<const float4*>(&Ws[k][tx * 4]);
            float av[4] = {a.x, a.y, a.z, a.w};
            float bv[4] = {b.x, b.y, b.z, b.w};
            #pragma unroll
            for (int i = 0; i < 4; i++)
                #pragma unroll
                for (int j = 0; j < 4; j++)
                    acc[i][j] = fmaf(av[i], bv[j], acc[i][j]);
        }
        __syncthreads();
    }

    #pragma unroll
    for (int i = 0; i < 4; i++) {
        const int m = m0 + ty * 4 + i;
        float ss = 0.0f;
        #pragma unroll
        for (int j = 0; j < 4; j++) {
            const int n = n0 + tx * 4 + j;
            float v = acc[i][j] + (bias ? bias[n] : 0.0f);
            if (ACT == 2) v = (v > 0.0f) ? v : 0.01f * v;
            C[m * Nc + n] = v;
            if (EMIT) {
                d_X2[m * 128 + n] = __float2bfloat16(v);
                ss = fmaf(v, v, ss);
            }
        }
        if (EMIT) {
            #pragma unroll
            for (int o = 8; o > 0; o >>= 1)
                ss += __shfl_xor_sync(0xFFFFFFFFu, ss, o);
            if (tx == 0) {
                if (n0 == 0) d_sqA[m] = ss; else d_sqB[m] = ss;
            }
        }
    }
}

// ---------------- fused P/Q GEMM: y=0 -> P = A@(Wa-Wb)+be, y=1 -> Q = A@Wb ----------
__global__ __launch_bounds__(256) void gemm_pq_kernel(const float* __restrict__ A,
                                                      const float* __restrict__ We,
                                                      const float* __restrict__ be,
                                                      float* __restrict__ P,
                                                      float* __restrict__ Q,
                                                      int Kd)
{
    __shared__ float As[16][64];
    __shared__ float Ws[16][64];
    const int m0 = blockIdx.x * 64;
    const int isQ = blockIdx.y;        // 0 -> P, 1 -> Q
    const int tid = threadIdx.x;
    const int tx = tid & 15;
    const int ty = tid >> 4;

    float acc[4][4];
    #pragma unroll
    for (int i = 0; i < 4; i++)
        #pragma unroll
        for (int j = 0; j < 4; j++) acc[i][j] = 0.0f;

    for (int k0 = 0; k0 < Kd; k0 += 16) {
        {
            const int m  = tid >> 2;
            const int kq = (tid & 3) * 4;
            float4 v = *reinterpret_cast<const float4*>(&A[(m0 + m) * Kd + k0 + kq]);
            As[kq + 0][m] = v.x; As[kq + 1][m] = v.y;
            As[kq + 2][m] = v.z; As[kq + 3][m] = v.w;
            const int kk = tid >> 4;
            const int nq = (tid & 15) * 4;
            float4 wb = *reinterpret_cast<const float4*>(&We[(Kd + k0 + kk) * 64 + nq]);
            if (!isQ) {
                float4 wa = *reinterpret_cast<const float4*>(&We[(k0 + kk) * 64 + nq]);
                wb.x = wa.x - wb.x; wb.y = wa.y - wb.y;
                wb.z = wa.z - wb.z; wb.w = wa.w - wb.w;
            }
            *reinterpret_cast<float4*>(&Ws[kk][nq]) = wb;
        }
        __syncthreads();
        #pragma unroll
        for (int k = 0; k < 16; k++) {
            float4 a = *reinterpret_cast<const float4*>(&As[k][ty * 4]);
            float4 b = *reinterpret_cast<const float4*>(&Ws[k][tx * 4]);
            float av[4] = {a.x, a.y, a.z, a.w};
            float bv[4] = {b.x, b.y, b.z, b.w};
            #pragma unroll
            for (int i = 0; i < 4; i++)
                #pragma unroll
                for (int j = 0; j < 4; j++)
                    acc[i][j] = fmaf(av[i], bv[j], acc[i][j]);
        }
        __syncthreads();
    }

    float* C = isQ ? Q : P;
    #pragma unroll
    for (int i = 0; i < 4; i++) {
        const int m = m0 + ty * 4 + i;
        #pragma unroll
        for (int j = 0; j < 4; j++) {
            const int n = tx * 4 + j;
            float v = acc[i][j] + (isQ ? 0.0f : be[n]);
            C[m * 64 + n] = v;
        }
    }
}

// ---------------- top-k insert (generic length) ----------------
template <int M>
__device__ __forceinline__ void topk_insert(float (&topd)[M], int (&topi)[M],
                                            float dd, int ci)
{
    topd[M - 1] = dd; topi[M - 1] = ci;
    #pragma unroll
    for (int z = M - 2; z >= 0; z--) {
        if (topd[z] > topd[z + 1]) {
            float td = topd[z]; topd[z] = topd[z + 1]; topd[z + 1] = td;
            int   ti = topi[z]; topi[z] = topi[z + 1]; topi[z + 1] = ti;
        }
    }
}

// ---------------- approx KNN via mma.sync (single-term bf16 Gram), 512 threads ----
// 128 queries/block, 128-candidate tiles, 16 warps; warp = 32q x 32c patch.
// fp32 dist, single buffer; argmin-loop scan with CROSS-THREAD shared threshold:
// s_thr[q] holds some thread's 16th-best (upper bound on the query's true 16th-
// best), pruning other threads' scans early. Union of lists still contains the
// exact top-CAND set, so final candidates are unchanged.
template <int D>
__global__ __launch_bounds__(512, 1) void knn_mma_kernel(const float* __restrict__ sqA,
                                                         const float* __restrict__ sqB,
                                                         int* __restrict__ outCand)
{
    constexpr int PAD   = 8;
    constexpr int PB    = (D + PAD) * 2;        // tile smem row pitch in bytes
    constexpr int TILEB = 128 * PB;
    constexpr int CH    = D / 8;                // 16B chunks per row
    constexpr int GK    = D / 16;               // k-chunks

    extern __shared__ char smch[];
    char* qt  = smch;
    char* ct0 = smch + TILEB;
    char* ct1 = smch + 2 * TILEB;
    float* dist = reinterpret_cast<float*>(smch + 3 * TILEB);  // 128*132 floats

    __shared__ float s_sqc[2][128];
    __shared__ float s_thr[128];
    __shared__ float s_mg [128 * CAND];
    __shared__ int   s_mgi[128 * CAND];

    const int tid  = threadIdx.x;
    const int wid  = tid >> 5;
    const int lane = tid & 31;
    const int q0   = blockIdx.x * 128;

    const int mrow = (wid & 3) * 32;            // warp's query-row base
    const int ncol = (wid >> 2) * 32;           // warp's candidate-col base
    const int lrow = lane & 15;
    const int lkof = (lane >> 4) * 16;

    const uint32_t qtu  = smem_u32(qt);
    const uint32_t ctu0 = smem_u32(ct0);
    const uint32_t ctu1 = smem_u32(ct1);
    const uint32_t aBase = qtu + (mrow + lrow) * PB + lkof;
    const uint32_t bOff  = (ncol + lrow) * PB + lkof;

    {
        #pragma unroll
        for (int i = tid; i < 128 * CH; i += 512) {
            const int r  = i / CH;
            const int ch = i - r * CH;
            CP_ASYNC16(qtu + r * PB + ch * 16,
                       d_X2 + (size_t)(q0 + r) * D + ch * 8);
        }
        #pragma unroll
        for (int i = tid; i < 128 * CH; i += 512) {
            const int r  = i / CH;
            const int ch = i - r * CH;
            CP_ASYNC16(ctu0 + r * PB + ch * 16,
                       d_X2 + (size_t)r * D + ch * 8);
        }
        CP_COMMIT();
        if (tid < 128) {
            float s = sqA[tid];
            if (sqB) s += sqB[tid];
            s_sqc[0][tid] = s;
            s_thr[tid] = 1e30f;
        }
    }

    float topd[CAND]; int topi[CAND];
    #pragma unroll
    for (int i = 0; i < CAND; i++) { topd[i] = 1e30f; topi[i] = 0; }

    const int qmine = tid & 127;     // query owned for scanning
    const int grp   = tid >> 7;      // 0..3: quarter of the candidate tile
    const int cbase = grp * 32;

    // A fragments are loop-invariant; keep them in registers for D=64 (fits RF).
    uint32_t aFrag[(D == 64) ? GK : 1][2][4];

    // argmin-loop scan of this thread's 32-candidate segment (tile base cp0),
    // pruned by the shared per-query threshold.
    float* const myrow = &dist[(tid & 127) * 132 + cbase];
    auto scan_row = [&](int cp0) {
        float thr = fminf(topd[CAND - 1], s_thr[qmine]);
        bool wrote = false;
        while (true) {
            float bm = 1e30f; int ba = 0;
            #pragma unroll
            for (int cc = 0; cc < 8; cc++) {
                float4 v = *reinterpret_cast<const float4*>(&myrow[cc * 4]);
                if (v.x < bm) { bm = v.x; ba = cc * 4 + 0; }
                if (v.y < bm) { bm = v.y; ba = cc * 4 + 1; }
                if (v.z < bm) { bm = v.z; ba = cc * 4 + 2; }
                if (v.w < bm) { bm = v.w; ba = cc * 4 + 3; }
            }
            if (bm >= thr) break;
            topk_insert(topd, topi, bm, cp0 + cbase + ba);
            myrow[ba] = 1e30f;   // remove from pool (thread-exclusive segment)
            thr = fminf(topd[CAND - 1], thr);
            wrote = true;
        }
        if (wrote && topd[CAND - 1] < 1e29f) s_thr[qmine] = topd[CAND - 1];
    };

    const int T = N_NODES / 128;
    for (int t = 0; t < T; t++) {
        CP_WAIT0();
        __syncthreads();   // ct(t) resident; dist(t-1) writes visible

        if constexpr (D == 64) {
            if (t == 0) {   // qt resident now; hoist invariant A fragments
                #pragma unroll
                for (int g = 0; g < GK; g++)
                    #pragma unroll
                    for (int mt = 0; mt < 2; mt++)
                        LDSM4(aFrag[g][mt][0], aFrag[g][mt][1],
                              aFrag[g][mt][2], aFrag[g][mt][3],
                              aBase + mt * 16 * PB + g * 32);
            }
        }

        const uint32_t ctu = (t & 1) ? ctu1 : ctu0;
        if (t + 1 < T) {
            const uint32_t ctn = ((t + 1) & 1) ? ctu1 : ctu0;
            const int r0n = (t + 1) * 128;
            #pragma unroll
            for (int i = tid; i < 128 * CH; i += 512) {
                const int r  = i / CH;
                const int ch = i - r * CH;
                CP_ASYNC16(ctn + r * PB + ch * 16,
                           d_X2 + (size_t)(r0n + r) * D + ch * 8);
            }
            CP_COMMIT();
            if (tid < 128) {
                float s = sqA[r0n + tid];
                if (sqB) s += sqB[r0n + tid];
                s_sqc[(t + 1) & 1][tid] = s;
            }
        }

        // ---- Gram: warp 32q x 32c, m16n8k16 atoms ----
        float acc[2][4][4];
        #pragma unroll
        for (int mt = 0; mt < 2; mt++)
            #pragma unroll
            for (int nt = 0; nt < 4; nt++)
                #pragma unroll
                for (int r = 0; r < 4; r++) acc[mt][nt][r] = 0.0f;

        const uint32_t bBase = ctu + bOff;
        #pragma unroll
        for (int g = 0; g < GK; g++) {
            uint32_t a[2][4];
            if constexpr (D == 64) {
                #pragma unroll
                for (int mt = 0; mt < 2; mt++)
                    #pragma unroll
                    for (int r = 0; r < 4; r++) a[mt][r] = aFrag[g][mt][r];
            } else {
                #pragma unroll
                for (int mt = 0; mt < 2; mt++)
                    LDSM4(a[mt][0], a[mt][1], a[mt][2], a[mt][3],
                          aBase + mt * 16 * PB + g * 32);
            }
            uint32_t b[4][2];
            #pragma unroll
            for (int nb = 0; nb < 2; nb++) {
                uint32_t r0, r1, r2, r3;
                LDSM4(r0, r1, r2, r3, bBase + nb * 16 * PB + g * 32);
                b[nb * 2][0] = r0; b[nb * 2][1] = r2;
                b[nb * 2 + 1][0] = r1; b[nb * 2 + 1][1] = r3;
            }
            #pragma unroll
            for (int mt = 0; mt < 2; mt++)
                #pragma unroll
                for (int nt = 0; nt < 4; nt++)
                    MMA16816(acc[mt][nt], a[mt], b[nt]);
        }

        // ---- scan dist(t-1) — independent of MMA(t); fills its latency ----
        if (t > 0) scan_row((t - 1) * 128);
        __syncthreads();   // all scans done before dist rewrite

        // ---- write dist(t), fp32 ----
        const float* sq = s_sqc[t & 1];
        const int c0 = t * 128;

        #pragma unroll
        for (int mt = 0; mt < 2; mt++) {
            const int qA = mrow + mt * 16 + (lane >> 2);
            #pragma unroll
            for (int nt = 0; nt < 4; nt++) {
                const int c = ncol + nt * 8 + (lane & 3) * 2;
                const float s0 = sq[c], s1 = sq[c + 1];
                float2 v0, v1;
                v0.x = fmaf(-2.0f, acc[mt][nt][0], s0);
                v0.y = fmaf(-2.0f, acc[mt][nt][1], s1);
                v1.x = fmaf(-2.0f, acc[mt][nt][2], s0);
                v1.y = fmaf(-2.0f, acc[mt][nt][3], s1);
                const int dq = (q0 + qA) - (c0 + c);
                if (dq ==  0) v0.x = 1e30f;
                if (dq ==  1) v0.y = 1e30f;
                if (dq == -8) v1.x = 1e30f;
                if (dq == -7) v1.y = 1e30f;
                *reinterpret_cast<float2*>(&dist[qA * 132 + c])       = v0;
                *reinterpret_cast<float2*>(&dist[(qA + 8) * 132 + c]) = v1;
            }
        }
    }

    // final tile's scan
    __syncthreads();
    scan_row((T - 1) * 128);

    // ---- merge the four per-query quarters (3 rounds through one buffer) ----
    #pragma unroll 1
    for (int s = 1; s < 4; s++) {
        __syncthreads();
        if (grp == s) {
            #pragma unroll
            for (int i = 0; i < CAND; i++) {
                s_mg [qmine * CAND + i] = topd[i];
                s_mgi[qmine * CAND + i] = topi[i];
            }
        }
        __syncthreads();
        if (grp == 0) {
            #pragma unroll
            for (int i = 0; i < CAND; i++) {
                const float dd = s_mg[qmine * CAND + i];
                if (dd < topd[CAND - 1]) topk_insert(topd, topi, dd, s_mgi[qmine * CAND + i]);
            }
        }
    }
    if (grp == 0) {
        #pragma unroll
        for (int i = 0; i < CAND; i++) outCand[(q0 + qmine) * CAND + i] = topi[i];
    }
}

// ---------------- fused rescore + EdgeConv aggregation ----------------
template <int D, int FUSE>
__global__ void rescoreagg_kernel(const float* __restrict__ X,
                                  const float* __restrict__ sqA,
                                  const float* __restrict__ sqB,
                                  const int* __restrict__ cand,
                                  const float* __restrict__ P,
                                  const float* __restrict__ Q,
                                  float* __restrict__ g,
                                  float* __restrict__ sqnOut)
{
    constexpr int PL = D / 32;
    const int wid  = threadIdx.x >> 5;
    const int lane = threadIdx.x & 31;
    const int q    = blockIdx.x * 8 + wid;

    float xq[PL];
    #pragma unroll
    for (int i = 0; i < PL; i++) xq[i] = X[q * D + i * 32 + lane];

    float topd[KNN]; int topi[KNN];
    #pragma unroll
    for (int i = 0; i < KNN; i++) { topd[i] = 1e30f; topi[i] = 0; }

    #pragma unroll
    for (int j = 0; j < CAND; j++) {
        const int c = cand[q * CAND + j];
        float dot = 0.0f;
        #pragma unroll
        for (int i = 0; i < PL; i++) dot = fmaf(xq[i], X[c * D + i * 32 + lane], dot);
        #pragma unroll
        for (int o = 16; o > 0; o >>= 1) dot += __shfl_xor_sync(0xFFFFFFFFu, dot, o);
        float sc = sqA[c];
        if (sqB) sc += sqB[c];
        const float dd = fmaf(-2.0f, dot, sc);
        if (dd < topd[KNN - 1]) topk_insert(topd, topi, dd, c);
    }

    // ---- aggregation: every lane holds the full top-KNN index list ----
    const float p0 = P[q * 64 + lane];
    const float p1 = P[q * 64 + 32 + lane];
    float m0 = -1e30f, m1 = -1e30f;
    #pragma unroll
    for (int kk = 0; kk < KNN; kk++) {
        const int j = topi[kk];
        float v0 = p0 + Q[j * 64 + lane];
        float v1 = p1 + Q[j * 64 + 32 + lane];
        v0 = (v0 > 0.0f) ? v0 : 0.01f * v0;
        v1 = (v1 > 0.0f) ? v1 : 0.01f * v1;
        m0 = fmaxf(m0, v0);
        m1 = fmaxf(m1, v1);
    }
    g[q * 64 + lane]      = m0;
    g[q * 64 + 32 + lane] = m1;

    if (FUSE) {
        d_X2[q * 64 + lane]      = __float2bfloat16(m0);
        d_X2[q * 64 + 32 + lane] = __float2bfloat16(m1);
        float s = fmaf(m0, m0, m1 * m1);
        #pragma unroll
        for (int o = 16; o > 0; o >>= 1) s += __shfl_xor_sync(0xFFFFFFFFu, s, o);
        if (lane == 0) sqnOut[q] = s;
    }
}

// ---------------- classifier ----------------
__global__ void classifier_kernel(const float* __restrict__ Wc, const float* __restrict__ bc,
                                  float* __restrict__ out)
{
    const int tid = threadIdx.x;
    const int n = blockIdx.x * 16 + (tid >> 4);
    const int c = tid & 15;
    float acc = bc[c];
    const float* g1r = d_g1 + n * 64;
    const float* g2r = d_g2 + n * 64;
    #pragma unroll 8
    for (int o = 0; o < 64; o++) {
        acc = fmaf(g1r[o], Wc[o * 16 + c], acc);
        acc = fmaf(g2r[o], Wc[(64 + o) * 16 + c], acc);
    }
    out[n * 16 + c] = acc;
}

// ---------------- launch ----------------
extern "C" void kernel_launch(void* const* d_in, const int* in_sizes, int n_in,
                              void* d_out, int out_size)
{
    const float* node_feat = (const float*)d_in[0];
    const float* rf_feat   = (const float*)d_in[1];
    const float* txp_feat  = (const float*)d_in[2];
    const float* Wb  = (const float*)d_in[3];
    const float* bb  = (const float*)d_in[4];
    const float* Wr  = (const float*)d_in[5];
    const float* br  = (const float*)d_in[6];
    const float* Wt  = (const float*)d_in[7];
    const float* bt  = (const float*)d_in[8];
    const float* Wf  = (const float*)d_in[9];
    const float* bf  = (const float*)d_in[10];
    const float* We1 = (const float*)d_in[11];
    const float* be1 = (const float*)d_in[12];
    const float* We2 = (const float*)d_in[13];
    const float* be2 = (const float*)d_in[14];
    const float* Wc  = (const float*)d_in[15];
    const float* bc  = (const float*)d_in[16];
    float* out = (float*)d_out;

    void *pE, *pH, *pg1, *pg2, *pP, *pQ, *psqA, *psqB, *psq2, *pcand;
    cudaGetSymbolAddress(&pE,    d_E);
    cudaGetSymbolAddress(&pH,    d_H);
    cudaGetSymbolAddress(&pg1,   d_g1);
    cudaGetSymbolAddress(&pg2,   d_g2);
    cudaGetSymbolAddress(&pP,    d_P);
    cudaGetSymbolAddress(&pQ,    d_Qm);
    cudaGetSymbolAddress(&psqA,  d_sqA);
    cudaGetSymbolAddress(&psqB,  d_sqB);
    cudaGetSymbolAddress(&psq2,  d_sqn2);
    cudaGetSymbolAddress(&pcand, d_cand);

    const int smem1 = 3 * 128 * 272 + 128 * 132 * 4;
    const int smem2 = 3 * 128 * 144 + 128 * 132 * 4;
    cudaFuncSetAttribute(knn_mma_kernel<128>, cudaFuncAttributeMaxDynamicSharedMemorySize, smem1);
    cudaFuncSetAttribute(knn_mma_kernel<64>,  cudaFuncAttributeMaxDynamicSharedMemorySize, smem2);

    // stage 1: embeds + fusion (emits H, bf16 X2, partial sq-norms)
    embed_kernel<<<N_NODES, 192>>>(node_feat, rf_feat, txp_feat, Wb, bb, Wr, br, Wt, bt);
    gemm_kernel<2, 1><<<dim3(N_NODES / 64, 2), 256>>>((const float*)pE, Wf, bf,
                                                      (float*)pH, 192, 128);

    // EdgeConv 1  (gemm_pq before knn keeps knn<128> at profiled slot #4)
    gemm_pq_kernel<<<dim3(N_NODES / 64, 2), 256>>>((const float*)pH, We1, be1,
                                                   (float*)pP, (float*)pQ, 128);
    knn_mma_kernel<128><<<128, 512, smem1>>>((const float*)psqA, (const float*)psqB,
                                             (int*)pcand);
    rescoreagg_kernel<128, 1><<<N_NODES / 8, 256>>>((const float*)pH,
                                                    (const float*)psqA, (const float*)psqB,
                                                    (const int*)pcand,
                                                    (const float*)pP, (const float*)pQ,
                                                    (float*)pg1, (float*)psq2);

    // EdgeConv 2
    gemm_pq_kernel<<<dim3(N_NODES / 64, 2), 256>>>((const float*)pg1, We2, be2,
                                                   (float*)pP, (float*)pQ, 64);
    knn_mma_kernel<64><<<128, 512, smem2>>>((const float*)psq2, nullptr, (int*)pcand);
    rescoreagg_kernel<64, 0><<<N_NODES / 8, 256>>>((const float*)pg1,
                                                   (const float*)psq2, nullptr,
                                                   (const int*)pcand,
                                                   (const float*)pP, (const float*)pQ,
                                                   (float*)pg2, nullptr);

    // classifier
    classifier_kernel<<<N_NODES / 16, 256>>>(Wc, bc, out);
}